// round 13
// baseline (speedup 1.0000x reference)
#include <cuda_runtime.h>
#include <cuda_fp16.h>
#include <math.h>
#include <stdint.h>

#define D_MODEL 1024
#define NHEADS  16
#define HD      64
#define SEQ     2048
#define ROWS    4096   // B * SEQ
#define MLP     4096

// ---------------- scratch (static device memory; no allocs) ----------------
__device__ float g_q [2 * NHEADS * ROWS * HD]; // 16 MB: qh (heads 0-15) + kh1 (16-31)
__device__ float g_k [NHEADS * ROWS * HD];     // 16 MB -> kh2 half pool
__device__ float g_t0[ROWS * D_MODEL];         // enc half
__device__ float g_t1[ROWS * D_MODEL];         // fp32 gemm outputs
__device__ float g_x1[ROWS * D_MODEL];
__device__ float g_x2[ROWS * D_MODEL];
__device__ float g_h [ROWS * MLP];             // act half
__device__ half  g_ah[ROWS * MLP];             // 32 MB hid (GELU out)
__device__ half  g_w [14 * 1024 * 1024];       // 28 MB weight pool

// ---------------- PTX helpers ----------------
__device__ __forceinline__ uint32_t smem_u32(const void* p) {
    uint32_t a;
    asm("{ .reg .u64 t; cvta.to.shared.u64 t, %1; cvt.u32.u64 %0, t; }" : "=r"(a) : "l"(p));
    return a;
}
__device__ __forceinline__ void cp16(uint32_t dst, const void* src) {
    asm volatile("cp.async.cg.shared.global [%0], [%1], 16;" :: "r"(dst), "l"(src));
}
__device__ __forceinline__ void cp_commit() { asm volatile("cp.async.commit_group;"); }
template <int N> __device__ __forceinline__ void cp_wait() {
    asm volatile("cp.async.wait_group %0;" :: "n"(N) : "memory");
}
__device__ __forceinline__ void ldsm4(uint32_t* r, uint32_t a) {
    asm volatile("ldmatrix.sync.aligned.m8n8.x4.shared.b16 {%0,%1,%2,%3}, [%4];"
                 : "=r"(r[0]), "=r"(r[1]), "=r"(r[2]), "=r"(r[3]) : "r"(a));
}
__device__ __forceinline__ void ldsm4t(uint32_t* r, uint32_t a) {
    asm volatile("ldmatrix.sync.aligned.m8n8.x4.trans.shared.b16 {%0,%1,%2,%3}, [%4];"
                 : "=r"(r[0]), "=r"(r[1]), "=r"(r[2]), "=r"(r[3]) : "r"(a));
}
__device__ __forceinline__ void mma16816h(float* d, const uint32_t* a, const uint32_t* b) {
    asm volatile("mma.sync.aligned.m16n8k16.row.col.f32.f16.f16.f32 "
                 "{%0,%1,%2,%3}, {%4,%5,%6,%7}, {%8,%9}, {%0,%1,%2,%3};"
                 : "+f"(d[0]), "+f"(d[1]), "+f"(d[2]), "+f"(d[3])
                 : "r"(a[0]), "r"(a[1]), "r"(a[2]), "r"(a[3]), "r"(b[0]), "r"(b[1]));
}
__device__ __forceinline__ uint32_t packh(float a, float b) {
    __half2 t = __halves2half2(__float2half_rn(a), __float2half_rn(b));
    return *(uint32_t*)&t;
}

#define SWZ(x) ((x) ^ ((((uint32_t)(x)) >> 3) & 0x70))
#define SOFF(b) ((b) * 32768u)
#define GEMM_SMEM 98304
#define FLASH_SMEM 50176

// ---------------- HMMA fp16 GEMM (128x128, 3-stage, 256 thr, occ 2) -------
// EPI: 0 fp32 C; 1 single-half head-contig (supports N=2048 fused QK);
//      2 +bias fp32; 3 +bias+GELU half.
template <int EPI>
__global__ __launch_bounds__(256, 2)
void mma_gemm(const half* __restrict__ A, const half* __restrict__ W,
              const float* __restrict__ bias, float* __restrict__ C,
              half* __restrict__ Oh, int N, int K)
{
    extern __shared__ __align__(1024) char smem[];
    const uint32_t sb = smem_u32(smem);
    const int tid = threadIdx.x, wid = tid >> 5, lane = tid & 31;
    const int bx = blockIdx.x, by = blockIdx.y;
    const int rowA0 = by * 128, rowB0 = bx * 128;

    const int r7 = lane & 7;
    const int aRowBase = (wid & 1) * 64 + ((lane >> 3) & 1) * 8 + r7;
    const int aGranLane = lane >> 4;
    const int bRowBase = (wid >> 1) * 32 + ((lane >> 4) << 3) + r7;
    const int bGranLane = (lane >> 3) & 1;

    float acc[4][4][4];
#pragma unroll
    for (int i = 0; i < 4; i++)
#pragma unroll
        for (int j = 0; j < 4; j++)
#pragma unroll
            for (int v = 0; v < 4; v++) acc[i][j][v] = 0.f;

    const int NCH = K >> 6;

    auto load_chunk = [&](int i, int b) {
        const int k0 = i << 6;
        const uint32_t st = sb + SOFF(b);
#pragma unroll
        for (int it = 0; it < 4; it++) {
            const int c = tid + it * 256;
            const int r = c >> 3, q = c & 7;
            const uint32_t d = SWZ(r * 128 + q * 16);
            cp16(st + d,         A + (size_t)(rowA0 + r) * K + k0 + q * 8);
            cp16(st + 16384 + d, W + (size_t)(rowB0 + r) * K + k0 + q * 8);
        }
        cp_commit();
    };

    load_chunk(0, 0);
    load_chunk(1, 1);

    for (int i = 0; i < NCH; i++) {
        const int b = i % 3;
        if (i + 2 < NCH)      { load_chunk(i + 2, (i + 2) % 3); cp_wait<2>(); }
        else if (i + 1 < NCH) { cp_wait<1>(); }
        else                  { cp_wait<0>(); }
        __syncthreads();

        const uint32_t bA = sb + SOFF(b), bW = bA + 16384;
#pragma unroll
        for (int ks = 0; ks < 4; ks++) {
            const int ga = ((2 * ks + aGranLane) ^ r7) << 4;
            const int gb = ((2 * ks + bGranLane) ^ r7) << 4;
            uint32_t ah[4][4], bh[2][4];
#pragma unroll
            for (int mf = 0; mf < 4; mf++)
                ldsm4(ah[mf], bA + (uint32_t)(aRowBase + mf * 16) * 128 + ga);
#pragma unroll
            for (int ng = 0; ng < 2; ng++)
                ldsm4(bh[ng], bW + (uint32_t)(bRowBase + ng * 16) * 128 + gb);
#pragma unroll
            for (int mf = 0; mf < 4; mf++)
#pragma unroll
                for (int n8 = 0; n8 < 4; n8++)
                    mma16816h(acc[mf][n8], ah[mf], &bh[n8 >> 1][(n8 & 1) * 2]);
        }
        __syncthreads();
    }

    const int mrow0 = by * 128 + (wid & 1) * 64 + (lane >> 2);
    const int ncol0 = bx * 128 + (wid >> 1) * 32 + (lane & 3) * 2;
#pragma unroll
    for (int mf = 0; mf < 4; mf++) {
#pragma unroll
        for (int n8 = 0; n8 < 4; n8++) {
            const int c = ncol0 + n8 * 8;
#pragma unroll
            for (int half_i = 0; half_i < 2; half_i++) {
                const int r = mrow0 + mf * 16 + half_i * 8;
                float v0 = acc[mf][n8][half_i * 2], v1 = acc[mf][n8][half_i * 2 + 1];
                if (EPI == 2 || EPI == 3) { v0 += bias[c]; v1 += bias[c + 1]; }
                if (EPI == 3) {
                    v0 = 0.5f * v0 * (1.0f + erff(v0 * 0.70710678118654752f));
                    v1 = 0.5f * v1 * (1.0f + erff(v1 * 0.70710678118654752f));
                }
                if (EPI == 1) {
                    // head-contig; c may span 0..2047 for fused QK (heads 0..31)
                    const size_t i0 = (size_t)(c >> 6) * (ROWS * HD) + (size_t)r * HD + (c & 63);
                    *(__half2*)(Oh + i0) = __halves2half2(__float2half_rn(v0), __float2half_rn(v1));
                } else if (EPI == 3) {
                    const size_t i0 = (size_t)r * N + c;
                    *(__half2*)(Oh + i0) = __halves2half2(__float2half_rn(v0), __float2half_rn(v1));
                } else {
                    *(float2*)(C + (size_t)r * N + c) = make_float2(v0, v1);
                }
            }
        }
    }
}

// ---------------- conversion kernels ----------------
__global__ __launch_bounds__(256)
void tohalf(const float* __restrict__ in, half* __restrict__ hi, int n4)
{
    const int i = blockIdx.x * 256 + threadIdx.x;
    if (i >= n4) return;
    const float4 v = ((const float4*)in)[i];
    ((__half2*)hi)[2 * i]     = __halves2half2(__float2half_rn(v.x), __float2half_rn(v.y));
    ((__half2*)hi)[2 * i + 1] = __halves2half2(__float2half_rn(v.z), __float2half_rn(v.w));
}

template <int PERM>
__global__ __launch_bounds__(256)
void tsplit(const float* __restrict__ W, half* __restrict__ th, int K, int N)
{
    __shared__ float t[32][33];
    const int n0 = blockIdx.x * 32, k0 = blockIdx.y * 32;
    const int tx = threadIdx.x & 31, ty = threadIdx.x >> 5;
#pragma unroll
    for (int j = 0; j < 32; j += 8)
        t[ty + j][tx] = W[(size_t)(k0 + ty + j) * N + n0 + tx];
    __syncthreads();
#pragma unroll
    for (int j = 0; j < 32; j += 8) {
        const float v = t[tx][ty + j];
        const int ocol = n0 + ty + j;
        const int orow = k0 + tx;
        const int srow = (PERM & 1) ? ((ocol & 15) * 64 + (ocol >> 4)) : ocol;
        const int scol = (PERM & 2) ? ((orow & 15) * 64 + (orow >> 4)) : orow;
        th[(size_t)srow * K + scol] = __float2half_rn(v);
    }
}

// ---------------- HMMA fp16 flash attention (values == K) ----------------
template <bool MASKED>
__global__ __launch_bounds__(256, 2)
void flash_mma(const half* __restrict__ Qf, const half* __restrict__ Kf,
               const int* __restrict__ mask, half* __restrict__ Oh)
{
    extern __shared__ __align__(1024) char smem[];
    const uint32_t sb = smem_u32(smem);
    const uint32_t sQ = sb;
    const uint32_t sK = sb + 16384;
    float* sMf = (float*)(smem + 49152);
    const int tid = threadIdx.x, wid = tid >> 5, lane = tid & 31;
    const int r7 = lane & 7;
    const int head = blockIdx.y, bat = blockIdx.z;
    const int qr0 = blockIdx.x * 128;
    const size_t hoff = (size_t)head * ROWS * HD;
    const half* gQ = Qf + hoff + (size_t)(bat * SEQ + qr0) * HD;
    const half* gK = Kf + hoff + (size_t)bat * SEQ * HD;

#pragma unroll
    for (int it = 0; it < 4; it++) {
        const int c = tid + it * 256;
        const int r = c >> 3, q = c & 7;
        cp16(sQ + SWZ(r * 128 + q * 16), gQ + (size_t)r * HD + q * 8);
    }
    cp_commit();

    auto load_k = [&](int mt2) {
        const uint32_t kb = sK + (mt2 & 1) * 16384;
#pragma unroll
        for (int it = 0; it < 4; it++) {
            const int c = tid + it * 256;
            const int r = c >> 3, q = c & 7;
            cp16(kb + SWZ(r * 128 + q * 16), gK + (size_t)(mt2 * 128 + r) * HD + q * 8);
        }
        if (MASKED && tid < 128)
            sMf[(mt2 & 1) * 128 + tid] = (float)mask[bat * SEQ + mt2 * 128 + tid];
        cp_commit();
    };
    load_k(0);

    uint32_t aQ[4][4];
    cp_wait<1>();
    __syncthreads();
    {
        const int row = wid * 16 + ((lane >> 3) & 1) * 8 + r7;
        const int g = lane >> 4;
#pragma unroll
        for (int ks = 0; ks < 4; ks++)
            ldsm4(aQ[ks], sQ + (uint32_t)row * 128 + ((((ks << 1) + g) ^ r7) << 4));
    }

    float o[8][4];
#pragma unroll
    for (int j = 0; j < 8; j++) { o[j][0] = o[j][1] = o[j][2] = o[j][3] = 0.f; }
    float lsum0 = 0.f, lsum1 = 0.f;

    const int sRowB = ((lane >> 4) << 3) + r7;
    const int sGran = (lane >> 3) & 1;
    const int tRowB = ((lane >> 3) & 1) * 8 + r7;
    const int tGran = lane >> 4;

    for (int mt2 = 0; mt2 < SEQ / 128; mt2++) {
        const uint32_t kb = sK + (mt2 & 1) * 16384;
        if (mt2 + 1 < SEQ / 128) { load_k(mt2 + 1); cp_wait<1>(); }
        else                     { cp_wait<0>(); }
        __syncthreads();

#pragma unroll
        for (int sub = 0; sub < 2; sub++) {
            const uint32_t ks_base = kb + sub * 8192;
            float s[8][4];
#pragma unroll
            for (int j = 0; j < 8; j++) { s[j][0] = s[j][1] = s[j][2] = s[j][3] = 0.f; }
#pragma unroll
            for (int ks = 0; ks < 4; ks++) {
                const uint32_t gg = ((((ks << 1) + sGran) ^ r7) << 4);
#pragma unroll
                for (int ng = 0; ng < 4; ng++) {
                    uint32_t bh[4];
                    ldsm4(bh, ks_base + (uint32_t)(ng * 16 + sRowB) * 128 + gg);
                    mma16816h(s[2 * ng],     aQ[ks], bh);
                    mma16816h(s[2 * ng + 1], aQ[ks], bh + 2);
                }
            }

            uint32_t ph[8][2];
#pragma unroll
            for (int j = 0; j < 8; j++) {
                if (MASKED) {
                    const int c0 = (mt2 & 1) * 128 + sub * 64 + j * 8 + (lane & 3) * 2;
                    if (sMf[c0]     != 0.f) { s[j][0] = -1e9f; s[j][2] = -1e9f; }
                    if (sMf[c0 + 1] != 0.f) { s[j][1] = -1e9f; s[j][3] = -1e9f; }
                }
                const float p0 = __expf(s[j][0] * 0.125f);
                const float p1 = __expf(s[j][1] * 0.125f);
                const float p2 = __expf(s[j][2] * 0.125f);
                const float p3 = __expf(s[j][3] * 0.125f);
                lsum0 += p0 + p1; lsum1 += p2 + p3;
                ph[j][0] = packh(p0, p1);
                ph[j][1] = packh(p2, p3);
            }

#pragma unroll
            for (int m16 = 0; m16 < 4; m16++) {
                uint32_t ah[4] = {ph[2 * m16][0], ph[2 * m16][1], ph[2 * m16 + 1][0], ph[2 * m16 + 1][1]};
#pragma unroll
                for (int dt = 0; dt < 4; dt++) {
                    uint32_t bh[4];
                    ldsm4t(bh, ks_base + (uint32_t)(m16 * 16 + tRowB) * 128 +
                               ((((dt << 1) + tGran) ^ r7) << 4));
                    mma16816h(o[2 * dt],     ah, bh);
                    mma16816h(o[2 * dt + 1], ah, bh + 2);
                }
            }
        }
        __syncthreads();
    }

    lsum0 += __shfl_xor_sync(0xffffffffu, lsum0, 1);
    lsum0 += __shfl_xor_sync(0xffffffffu, lsum0, 2);
    lsum1 += __shfl_xor_sync(0xffffffffu, lsum1, 1);
    lsum1 += __shfl_xor_sync(0xffffffffu, lsum1, 2);
    const float inv0 = 1.0f / lsum0, inv1 = 1.0f / lsum1;

    const int grow0 = bat * SEQ + qr0 + wid * 16 + (lane >> 2);
#pragma unroll
    for (int j = 0; j < 8; j++) {
        const int d0 = j * 8 + (lane & 3) * 2;
        const size_t b0 = (size_t)grow0 * D_MODEL + head * 64 + d0;
        const size_t b1 = (size_t)(grow0 + 8) * D_MODEL + head * 64 + d0;
        *(__half2*)(Oh + b0) = __halves2half2(
            __float2half_rn(o[j][0] * inv0), __float2half_rn(o[j][1] * inv0));
        *(__half2*)(Oh + b1) = __halves2half2(
            __float2half_rn(o[j][2] * inv1), __float2half_rn(o[j][3] * inv1));
    }
}

// ---------------- fused residual + LayerNorm (+ optional half out) --------
template <bool TOH>
__global__ __launch_bounds__(256)
void add_ln_kernel(const float* __restrict__ X, const float* __restrict__ R,
                   const float* __restrict__ gg, const float* __restrict__ bb,
                   float* __restrict__ O, half* __restrict__ Oh)
{
    const int row = blockIdx.x, t = threadIdx.x;
    const float4 xv = ((const float4*)X)[(size_t)row * 256 + t];
    const float4 rv = ((const float4*)R)[(size_t)row * 256 + t];
    const float v0 = xv.x + rv.x, v1 = xv.y + rv.y, v2 = xv.z + rv.z, v3 = xv.w + rv.w;
    float s  = v0 + v1 + v2 + v3;
    float ss = v0 * v0 + v1 * v1 + v2 * v2 + v3 * v3;
#pragma unroll
    for (int o = 16; o; o >>= 1) {
        s  += __shfl_xor_sync(0xffffffffu, s,  o);
        ss += __shfl_xor_sync(0xffffffffu, ss, o);
    }
    __shared__ float sm[8], sm2[8];
    if ((t & 31) == 0) { sm[t >> 5] = s; sm2[t >> 5] = ss; }
    __syncthreads();
    float ts = 0.f, tss = 0.f;
#pragma unroll
    for (int i = 0; i < 8; i++) { ts += sm[i]; tss += sm2[i]; }
    const float mu   = ts * (1.0f / 1024.0f);
    const float var  = tss * (1.0f / 1024.0f) - mu * mu;
    const float istd = rsqrtf(var + 1e-5f);
    const float4 gv = ((const float4*)gg)[t];
    const float4 bv = ((const float4*)bb)[t];
    float4 ov;
    ov.x = (v0 - mu) * istd * gv.x + bv.x;
    ov.y = (v1 - mu) * istd * gv.y + bv.y;
    ov.z = (v2 - mu) * istd * gv.z + bv.z;
    ov.w = (v3 - mu) * istd * gv.w + bv.w;
    ((float4*)O)[(size_t)row * 256 + t] = ov;
    if (TOH) {
        const size_t base = (size_t)row * 512 + 2 * t;
        ((__half2*)Oh)[base]     = __halves2half2(__float2half_rn(ov.x), __float2half_rn(ov.y));
        ((__half2*)Oh)[base + 1] = __halves2half2(__float2half_rn(ov.z), __float2half_rn(ov.w));
    }
}

// ---------------- launcher ----------------
extern "C" void kernel_launch(void* const* d_in, const int* in_sizes, int n_in,
                              void* d_out, int out_size)
{
    (void)in_sizes; (void)n_in; (void)out_size;
    const float* x    = (const float*)d_in[0];
    const float* enc  = (const float*)d_in[1];
    const int*   mask = (const int*)  d_in[2];
    const float* q1W  = (const float*)d_in[3];
    const float* w1W  = (const float*)d_in[4];
    const float* o1W  = (const float*)d_in[5];
    const float* q2W  = (const float*)d_in[6];
    const float* w2W  = (const float*)d_in[7];
    const float* o2W  = (const float*)d_in[8];
    const float* ffW1 = (const float*)d_in[9];
    const float* ffb1 = (const float*)d_in[10];
    const float* ffW2 = (const float*)d_in[11];
    const float* ffb2 = (const float*)d_in[12];
    const float* g1   = (const float*)d_in[13];
    const float* b1   = (const float*)d_in[14];
    const float* g2   = (const float*)d_in[15];
    const float* b2   = (const float*)d_in[16];
    const float* g3   = (const float*)d_in[17];
    const float* b3   = (const float*)d_in[18];

    float *pq, *pk, *pt0, *pt1, *px1, *px2, *phd;
    half *hid, *wpool;
    cudaGetSymbolAddress((void**)&pq,    g_q);
    cudaGetSymbolAddress((void**)&pk,    g_k);
    cudaGetSymbolAddress((void**)&pt0,   g_t0);
    cudaGetSymbolAddress((void**)&pt1,   g_t1);
    cudaGetSymbolAddress((void**)&px1,   g_x1);
    cudaGetSymbolAddress((void**)&px2,   g_x2);
    cudaGetSymbolAddress((void**)&phd,   g_h);
    cudaGetSymbolAddress((void**)&hid,   g_ah);
    cudaGetSymbolAddress((void**)&wpool, g_w);

    half* actH = (half*)phd;
    half* encH = (half*)pt0;
    half* qh   = (half*)pq;                         // heads 0-15 = Q
    half* kh1  = qh + (size_t)NHEADS * ROWS * HD;   // heads 16-31 = K (self)
    half* kh2  = (half*)pk;
    const size_t M1 = 1024 * 1024;
    half* wQK1 = wpool;                 // 2 MB-halves: q1W^T rows 0-1023, w1W^T rows 1024-2047
    half* wO1  = wpool + 2 * M1;
    half* wQ2  = wpool + 3 * M1;
    half* wK2  = wpool + 4 * M1;
    half* wO2  = wpool + 5 * M1;
    half* wF1  = wpool + 6 * M1;
    half* wF2  = wpool + 10 * M1;

    static cudaStream_t s2 = nullptr;
    static cudaEvent_t evFork, evQK1, evO1, evQ2, evO2, evF1, evF2, evK2;
    if (!s2) {
        cudaStreamCreateWithFlags(&s2, cudaStreamNonBlocking);
        cudaEventCreateWithFlags(&evFork, cudaEventDisableTiming);
        cudaEventCreateWithFlags(&evQK1,  cudaEventDisableTiming);
        cudaEventCreateWithFlags(&evO1,   cudaEventDisableTiming);
        cudaEventCreateWithFlags(&evQ2,   cudaEventDisableTiming);
        cudaEventCreateWithFlags(&evO2,   cudaEventDisableTiming);
        cudaEventCreateWithFlags(&evF1,   cudaEventDisableTiming);
        cudaEventCreateWithFlags(&evF2,   cudaEventDisableTiming);
        cudaEventCreateWithFlags(&evK2,   cudaEventDisableTiming);
        cudaFuncSetAttribute(mma_gemm<0>, cudaFuncAttributeMaxDynamicSharedMemorySize, GEMM_SMEM);
        cudaFuncSetAttribute(mma_gemm<1>, cudaFuncAttributeMaxDynamicSharedMemorySize, GEMM_SMEM);
        cudaFuncSetAttribute(mma_gemm<2>, cudaFuncAttributeMaxDynamicSharedMemorySize, GEMM_SMEM);
        cudaFuncSetAttribute(mma_gemm<3>, cudaFuncAttributeMaxDynamicSharedMemorySize, GEMM_SMEM);
        cudaFuncSetAttribute(flash_mma<false>, cudaFuncAttributeMaxDynamicSharedMemorySize, FLASH_SMEM);
        cudaFuncSetAttribute(flash_mma<true>,  cudaFuncAttributeMaxDynamicSharedMemorySize, FLASH_SMEM);
    }

    const dim3 gP(D_MODEL / 128, ROWS / 128);    // (8, 32)
    const dim3 gQK(2 * D_MODEL / 128, ROWS / 128); // (16, 32) fused QK
    const dim3 gF1g(MLP / 128, ROWS / 128);      // (32, 32)
    const dim3 gAttn(SEQ / 128, NHEADS, 2);
    const dim3 tW(D_MODEL / 32, D_MODEL / 32);
    const dim3 tW1(MLP / 32, D_MODEL / 32);
    const dim3 tW2(D_MODEL / 32, MLP / 32);
    const int n4_act = ROWS * D_MODEL / 4;

    // ---- side stream: weights by deadline + cross-attn K chain ----
    cudaEventRecord(evFork, 0);
    cudaStreamWaitEvent(s2, evFork, 0);
    tsplit<1><<<tW, 256, 0, s2>>>(q1W, wQK1, D_MODEL, D_MODEL);
    tsplit<1><<<tW, 256, 0, s2>>>(w1W, wQK1 + M1, D_MODEL, D_MODEL);
    cudaEventRecord(evQK1, s2);
    tsplit<2><<<tW, 256, 0, s2>>>(o1W, wO1, D_MODEL, D_MODEL);
    cudaEventRecord(evO1, s2);
    tsplit<1><<<tW, 256, 0, s2>>>(q2W, wQ2, D_MODEL, D_MODEL);
    cudaEventRecord(evQ2, s2);
    tohalf<<<(n4_act + 255) / 256, 256, 0, s2>>>(enc, encH, n4_act);
    tsplit<1><<<tW, 256, 0, s2>>>(w2W, wK2, D_MODEL, D_MODEL);
    mma_gemm<1><<<gP, 256, GEMM_SMEM, s2>>>(encH, wK2, nullptr, nullptr, kh2, D_MODEL, D_MODEL);
    cudaEventRecord(evK2, s2);
    tsplit<2><<<tW, 256, 0, s2>>>(o2W, wO2, D_MODEL, D_MODEL);
    cudaEventRecord(evO2, s2);
    tsplit<0><<<tW1, 256, 0, s2>>>(ffW1, wF1, D_MODEL, MLP);
    cudaEventRecord(evF1, s2);
    tsplit<0><<<tW2, 256, 0, s2>>>(ffW2, wF2, MLP, D_MODEL);
    cudaEventRecord(evF2, s2);

    // ---- main chain: self-attention (fused QK projection) ----
    tohalf<<<(n4_act + 255) / 256, 256>>>(x, actH, n4_act);
    cudaStreamWaitEvent(0, evQK1, 0);
    mma_gemm<1><<<gQK, 256, GEMM_SMEM>>>(actH, wQK1, nullptr, nullptr, qh, 2 * D_MODEL, D_MODEL);
    flash_mma<false><<<gAttn, 256, FLASH_SMEM>>>(qh, kh1, nullptr, actH);
    cudaStreamWaitEvent(0, evO1, 0);
    mma_gemm<0><<<gP, 256, GEMM_SMEM>>>(actH, wO1, nullptr, pt1, nullptr, D_MODEL, D_MODEL);
    add_ln_kernel<true><<<ROWS, 256>>>(x, pt1, g1, b1, px1, actH);

    // ---- cross-attention (masked) ----
    cudaStreamWaitEvent(0, evQ2, 0);
    mma_gemm<1><<<gP, 256, GEMM_SMEM>>>(actH, wQ2, nullptr, nullptr, qh, D_MODEL, D_MODEL);
    cudaStreamWaitEvent(0, evK2, 0);
    flash_mma<true><<<gAttn, 256, FLASH_SMEM>>>(qh, kh2, mask, actH);
    cudaStreamWaitEvent(0, evO2, 0);
    mma_gemm<0><<<gP, 256, GEMM_SMEM>>>(actH, wO2, nullptr, pt1, nullptr, D_MODEL, D_MODEL);
    add_ln_kernel<true><<<ROWS, 256>>>(px1, pt1, g2, b2, px2, actH);

    // ---- feed-forward ----
    cudaStreamWaitEvent(0, evF1, 0);
    mma_gemm<3><<<gF1g, 256, GEMM_SMEM>>>(actH, wF1, ffb1, nullptr, hid, MLP, D_MODEL);
    cudaStreamWaitEvent(0, evF2, 0);
    mma_gemm<2><<<gP, 256, GEMM_SMEM>>>(hid, wF2, ffb2, pt1, nullptr, D_MODEL, MLP);
    add_ln_kernel<false><<<ROWS, 256>>>(px2, pt1, g3, b3, (float*)d_out, nullptr);
}

// round 14
// speedup vs baseline: 1.5160x; 1.5160x over previous
#include <cuda_runtime.h>
#include <cuda_fp16.h>
#include <math.h>
#include <stdint.h>

#define D_MODEL 1024
#define NHEADS  16
#define HD      64
#define SEQ     2048
#define ROWS    4096   // B * SEQ
#define MLP     4096

// ---------------- scratch (static device memory; no allocs) ----------------
__device__ float g_q [NHEADS * ROWS * HD];     // 16 MB -> qh half pool
__device__ float g_k [NHEADS * ROWS * HD];     // 16 MB -> kh1 + kh2 half pools
__device__ float g_t0[ROWS * D_MODEL];         // enc half
__device__ float g_t1[ROWS * D_MODEL];         // fp32 gemm outputs
__device__ float g_x1[ROWS * D_MODEL];
__device__ float g_x2[ROWS * D_MODEL];
__device__ float g_h [ROWS * MLP];             // act half
__device__ half  g_ah[ROWS * MLP];             // 32 MB hid (GELU out)
__device__ half  g_w [14 * 1024 * 1024];       // 28 MB weight pool

// ---------------- PTX helpers ----------------
__device__ __forceinline__ uint32_t smem_u32(const void* p) {
    uint32_t a;
    asm("{ .reg .u64 t; cvta.to.shared.u64 t, %1; cvt.u32.u64 %0, t; }" : "=r"(a) : "l"(p));
    return a;
}
__device__ __forceinline__ void cp16(uint32_t dst, const void* src) {
    asm volatile("cp.async.cg.shared.global [%0], [%1], 16;" :: "r"(dst), "l"(src));
}
__device__ __forceinline__ void cp_commit() { asm volatile("cp.async.commit_group;"); }
template <int N> __device__ __forceinline__ void cp_wait() {
    asm volatile("cp.async.wait_group %0;" :: "n"(N) : "memory");
}
__device__ __forceinline__ void ldsm4(uint32_t* r, uint32_t a) {
    asm volatile("ldmatrix.sync.aligned.m8n8.x4.shared.b16 {%0,%1,%2,%3}, [%4];"
                 : "=r"(r[0]), "=r"(r[1]), "=r"(r[2]), "=r"(r[3]) : "r"(a));
}
__device__ __forceinline__ void ldsm4t(uint32_t* r, uint32_t a) {
    asm volatile("ldmatrix.sync.aligned.m8n8.x4.trans.shared.b16 {%0,%1,%2,%3}, [%4];"
                 : "=r"(r[0]), "=r"(r[1]), "=r"(r[2]), "=r"(r[3]) : "r"(a));
}
__device__ __forceinline__ void mma16816h(float* d, const uint32_t* a, const uint32_t* b) {
    asm volatile("mma.sync.aligned.m16n8k16.row.col.f32.f16.f16.f32 "
                 "{%0,%1,%2,%3}, {%4,%5,%6,%7}, {%8,%9}, {%0,%1,%2,%3};"
                 : "+f"(d[0]), "+f"(d[1]), "+f"(d[2]), "+f"(d[3])
                 : "r"(a[0]), "r"(a[1]), "r"(a[2]), "r"(a[3]), "r"(b[0]), "r"(b[1]));
}
__device__ __forceinline__ uint32_t packh(float a, float b) {
    __half2 t = __halves2half2(__float2half_rn(a), __float2half_rn(b));
    return *(uint32_t*)&t;
}

#define SWZ(x) ((x) ^ ((((uint32_t)(x)) >> 3) & 0x70))
#define SOFF(b) ((b) * 32768u)
#define GEMM_SMEM 98304
#define FLASH_SMEM 50176

// ---------------- HMMA fp16 GEMM (128x128, 3-stage, 256 thr, occ 2) -------
// EPI: 0 fp32 C; 1 single-half head-contig; 2 +bias fp32; 3 +bias+GELU half.
template <int EPI>
__global__ __launch_bounds__(256, 2)
void mma_gemm(const half* __restrict__ A, const half* __restrict__ W,
              const float* __restrict__ bias, float* __restrict__ C,
              half* __restrict__ Oh, int N, int K)
{
    extern __shared__ __align__(1024) char smem[];
    const uint32_t sb = smem_u32(smem);
    const int tid = threadIdx.x, wid = tid >> 5, lane = tid & 31;
    const int bx = blockIdx.x, by = blockIdx.y;
    const int rowA0 = by * 128, rowB0 = bx * 128;

    const int r7 = lane & 7;
    const int aRowBase = (wid & 1) * 64 + ((lane >> 3) & 1) * 8 + r7;
    const int aGranLane = lane >> 4;
    const int bRowBase = (wid >> 1) * 32 + ((lane >> 4) << 3) + r7;
    const int bGranLane = (lane >> 3) & 1;

    float acc[4][4][4];
#pragma unroll
    for (int i = 0; i < 4; i++)
#pragma unroll
        for (int j = 0; j < 4; j++)
#pragma unroll
            for (int v = 0; v < 4; v++) acc[i][j][v] = 0.f;

    const int NCH = K >> 6;

    auto load_chunk = [&](int i, int b) {
        const int k0 = i << 6;
        const uint32_t st = sb + SOFF(b);
#pragma unroll
        for (int it = 0; it < 4; it++) {
            const int c = tid + it * 256;
            const int r = c >> 3, q = c & 7;
            const uint32_t d = SWZ(r * 128 + q * 16);
            cp16(st + d,         A + (size_t)(rowA0 + r) * K + k0 + q * 8);
            cp16(st + 16384 + d, W + (size_t)(rowB0 + r) * K + k0 + q * 8);
        }
        cp_commit();
    };

    load_chunk(0, 0);
    load_chunk(1, 1);

    for (int i = 0; i < NCH; i++) {
        const int b = i % 3;
        if (i + 2 < NCH)      { load_chunk(i + 2, (i + 2) % 3); cp_wait<2>(); }
        else if (i + 1 < NCH) { cp_wait<1>(); }
        else                  { cp_wait<0>(); }
        __syncthreads();

        const uint32_t bA = sb + SOFF(b), bW = bA + 16384;
#pragma unroll
        for (int ks = 0; ks < 4; ks++) {
            const int ga = ((2 * ks + aGranLane) ^ r7) << 4;
            const int gb = ((2 * ks + bGranLane) ^ r7) << 4;
            uint32_t ah[4][4], bh[2][4];
#pragma unroll
            for (int mf = 0; mf < 4; mf++)
                ldsm4(ah[mf], bA + (uint32_t)(aRowBase + mf * 16) * 128 + ga);
#pragma unroll
            for (int ng = 0; ng < 2; ng++)
                ldsm4(bh[ng], bW + (uint32_t)(bRowBase + ng * 16) * 128 + gb);
#pragma unroll
            for (int mf = 0; mf < 4; mf++)
#pragma unroll
                for (int n8 = 0; n8 < 4; n8++)
                    mma16816h(acc[mf][n8], ah[mf], &bh[n8 >> 1][(n8 & 1) * 2]);
        }
        __syncthreads();
    }

    const int mrow0 = by * 128 + (wid & 1) * 64 + (lane >> 2);
    const int ncol0 = bx * 128 + (wid >> 1) * 32 + (lane & 3) * 2;
#pragma unroll
    for (int mf = 0; mf < 4; mf++) {
#pragma unroll
        for (int n8 = 0; n8 < 4; n8++) {
            const int c = ncol0 + n8 * 8;
#pragma unroll
            for (int half_i = 0; half_i < 2; half_i++) {
                const int r = mrow0 + mf * 16 + half_i * 8;
                float v0 = acc[mf][n8][half_i * 2], v1 = acc[mf][n8][half_i * 2 + 1];
                if (EPI == 2 || EPI == 3) { v0 += bias[c]; v1 += bias[c + 1]; }
                if (EPI == 3) {
                    v0 = 0.5f * v0 * (1.0f + erff(v0 * 0.70710678118654752f));
                    v1 = 0.5f * v1 * (1.0f + erff(v1 * 0.70710678118654752f));
                }
                if (EPI == 1) {
                    const size_t i0 = (size_t)(c >> 6) * (ROWS * HD) + (size_t)r * HD + (c & 63);
                    *(__half2*)(Oh + i0) = __halves2half2(__float2half_rn(v0), __float2half_rn(v1));
                } else if (EPI == 3) {
                    const size_t i0 = (size_t)r * N + c;
                    *(__half2*)(Oh + i0) = __halves2half2(__float2half_rn(v0), __float2half_rn(v1));
                } else {
                    *(float2*)(C + (size_t)r * N + c) = make_float2(v0, v1);
                }
            }
        }
    }
}

// ---------------- conversion kernels ----------------
__global__ __launch_bounds__(256)
void tohalf(const float* __restrict__ in, half* __restrict__ hi, int n4)
{
    const int i = blockIdx.x * 256 + threadIdx.x;
    if (i >= n4) return;
    const float4 v = ((const float4*)in)[i];
    ((__half2*)hi)[2 * i]     = __halves2half2(__float2half_rn(v.x), __float2half_rn(v.y));
    ((__half2*)hi)[2 * i + 1] = __halves2half2(__float2half_rn(v.z), __float2half_rn(v.w));
}

template <int PERM>
__global__ __launch_bounds__(256)
void tsplit(const float* __restrict__ W, half* __restrict__ th, int K, int N)
{
    __shared__ float t[32][33];
    const int n0 = blockIdx.x * 32, k0 = blockIdx.y * 32;
    const int tx = threadIdx.x & 31, ty = threadIdx.x >> 5;
#pragma unroll
    for (int j = 0; j < 32; j += 8)
        t[ty + j][tx] = W[(size_t)(k0 + ty + j) * N + n0 + tx];
    __syncthreads();
#pragma unroll
    for (int j = 0; j < 32; j += 8) {
        const float v = t[tx][ty + j];
        const int ocol = n0 + ty + j;
        const int orow = k0 + tx;
        const int srow = (PERM & 1) ? ((ocol & 15) * 64 + (ocol >> 4)) : ocol;
        const int scol = (PERM & 2) ? ((orow & 15) * 64 + (orow >> 4)) : orow;
        th[(size_t)srow * K + scol] = __float2half_rn(v);
    }
}

// ---------------- HMMA fp16 flash attention (values == K) ----------------
template <bool MASKED>
__global__ __launch_bounds__(256, 2)
void flash_mma(const half* __restrict__ Qf, const half* __restrict__ Kf,
               const int* __restrict__ mask, half* __restrict__ Oh)
{
    extern __shared__ __align__(1024) char smem[];
    const uint32_t sb = smem_u32(smem);
    const uint32_t sQ = sb;
    const uint32_t sK = sb + 16384;
    float* sMf = (float*)(smem + 49152);
    const int tid = threadIdx.x, wid = tid >> 5, lane = tid & 31;
    const int r7 = lane & 7;
    const int head = blockIdx.y, bat = blockIdx.z;
    const int qr0 = blockIdx.x * 128;
    const size_t hoff = (size_t)head * ROWS * HD;
    const half* gQ = Qf + hoff + (size_t)(bat * SEQ + qr0) * HD;
    const half* gK = Kf + hoff + (size_t)bat * SEQ * HD;

#pragma unroll
    for (int it = 0; it < 4; it++) {
        const int c = tid + it * 256;
        const int r = c >> 3, q = c & 7;
        cp16(sQ + SWZ(r * 128 + q * 16), gQ + (size_t)r * HD + q * 8);
    }
    cp_commit();

    auto load_k = [&](int mt2) {
        const uint32_t kb = sK + (mt2 & 1) * 16384;
#pragma unroll
        for (int it = 0; it < 4; it++) {
            const int c = tid + it * 256;
            const int r = c >> 3, q = c & 7;
            cp16(kb + SWZ(r * 128 + q * 16), gK + (size_t)(mt2 * 128 + r) * HD + q * 8);
        }
        if (MASKED && tid < 128)
            sMf[(mt2 & 1) * 128 + tid] = (float)mask[bat * SEQ + mt2 * 128 + tid];
        cp_commit();
    };
    load_k(0);

    uint32_t aQ[4][4];
    cp_wait<1>();
    __syncthreads();
    {
        const int row = wid * 16 + ((lane >> 3) & 1) * 8 + r7;
        const int g = lane >> 4;
#pragma unroll
        for (int ks = 0; ks < 4; ks++)
            ldsm4(aQ[ks], sQ + (uint32_t)row * 128 + ((((ks << 1) + g) ^ r7) << 4));
    }

    float o[8][4];
#pragma unroll
    for (int j = 0; j < 8; j++) { o[j][0] = o[j][1] = o[j][2] = o[j][3] = 0.f; }
    float lsum0 = 0.f, lsum1 = 0.f;

    const int sRowB = ((lane >> 4) << 3) + r7;
    const int sGran = (lane >> 3) & 1;
    const int tRowB = ((lane >> 3) & 1) * 8 + r7;
    const int tGran = lane >> 4;

    for (int mt2 = 0; mt2 < SEQ / 128; mt2++) {
        const uint32_t kb = sK + (mt2 & 1) * 16384;
        if (mt2 + 1 < SEQ / 128) { load_k(mt2 + 1); cp_wait<1>(); }
        else                     { cp_wait<0>(); }
        __syncthreads();

#pragma unroll
        for (int sub = 0; sub < 2; sub++) {
            const uint32_t ks_base = kb + sub * 8192;
            float s[8][4];
#pragma unroll
            for (int j = 0; j < 8; j++) { s[j][0] = s[j][1] = s[j][2] = s[j][3] = 0.f; }
#pragma unroll
            for (int ks = 0; ks < 4; ks++) {
                const uint32_t gg = ((((ks << 1) + sGran) ^ r7) << 4);
#pragma unroll
                for (int ng = 0; ng < 4; ng++) {
                    uint32_t bh[4];
                    ldsm4(bh, ks_base + (uint32_t)(ng * 16 + sRowB) * 128 + gg);
                    mma16816h(s[2 * ng],     aQ[ks], bh);
                    mma16816h(s[2 * ng + 1], aQ[ks], bh + 2);
                }
            }

            uint32_t ph[8][2];
#pragma unroll
            for (int j = 0; j < 8; j++) {
                if (MASKED) {
                    const int c0 = (mt2 & 1) * 128 + sub * 64 + j * 8 + (lane & 3) * 2;
                    if (sMf[c0]     != 0.f) { s[j][0] = -1e9f; s[j][2] = -1e9f; }
                    if (sMf[c0 + 1] != 0.f) { s[j][1] = -1e9f; s[j][3] = -1e9f; }
                }
                const float p0 = __expf(s[j][0] * 0.125f);
                const float p1 = __expf(s[j][1] * 0.125f);
                const float p2 = __expf(s[j][2] * 0.125f);
                const float p3 = __expf(s[j][3] * 0.125f);
                lsum0 += p0 + p1; lsum1 += p2 + p3;
                ph[j][0] = packh(p0, p1);
                ph[j][1] = packh(p2, p3);
            }

#pragma unroll
            for (int m16 = 0; m16 < 4; m16++) {
                uint32_t ah[4] = {ph[2 * m16][0], ph[2 * m16][1], ph[2 * m16 + 1][0], ph[2 * m16 + 1][1]};
#pragma unroll
                for (int dt = 0; dt < 4; dt++) {
                    uint32_t bh[4];
                    ldsm4t(bh, ks_base + (uint32_t)(m16 * 16 + tRowB) * 128 +
                               ((((dt << 1) + tGran) ^ r7) << 4));
                    mma16816h(o[2 * dt],     ah, bh);
                    mma16816h(o[2 * dt + 1], ah, bh + 2);
                }
            }
        }
        __syncthreads();
    }

    lsum0 += __shfl_xor_sync(0xffffffffu, lsum0, 1);
    lsum0 += __shfl_xor_sync(0xffffffffu, lsum0, 2);
    lsum1 += __shfl_xor_sync(0xffffffffu, lsum1, 1);
    lsum1 += __shfl_xor_sync(0xffffffffu, lsum1, 2);
    const float inv0 = 1.0f / lsum0, inv1 = 1.0f / lsum1;

    const int grow0 = bat * SEQ + qr0 + wid * 16 + (lane >> 2);
#pragma unroll
    for (int j = 0; j < 8; j++) {
        const int d0 = j * 8 + (lane & 3) * 2;
        const size_t b0 = (size_t)grow0 * D_MODEL + head * 64 + d0;
        const size_t b1 = (size_t)(grow0 + 8) * D_MODEL + head * 64 + d0;
        *(__half2*)(Oh + b0) = __halves2half2(
            __float2half_rn(o[j][0] * inv0), __float2half_rn(o[j][1] * inv0));
        *(__half2*)(Oh + b1) = __halves2half2(
            __float2half_rn(o[j][2] * inv1), __float2half_rn(o[j][3] * inv1));
    }
}

// ---------------- fused residual + LayerNorm (+ optional half out) --------
template <bool TOH>
__global__ __launch_bounds__(256)
void add_ln_kernel(const float* __restrict__ X, const float* __restrict__ R,
                   const float* __restrict__ gg, const float* __restrict__ bb,
                   float* __restrict__ O, half* __restrict__ Oh)
{
    const int row = blockIdx.x, t = threadIdx.x;
    const float4 xv = ((const float4*)X)[(size_t)row * 256 + t];
    const float4 rv = ((const float4*)R)[(size_t)row * 256 + t];
    const float v0 = xv.x + rv.x, v1 = xv.y + rv.y, v2 = xv.z + rv.z, v3 = xv.w + rv.w;
    float s  = v0 + v1 + v2 + v3;
    float ss = v0 * v0 + v1 * v1 + v2 * v2 + v3 * v3;
#pragma unroll
    for (int o = 16; o; o >>= 1) {
        s  += __shfl_xor_sync(0xffffffffu, s,  o);
        ss += __shfl_xor_sync(0xffffffffu, ss, o);
    }
    __shared__ float sm[8], sm2[8];
    if ((t & 31) == 0) { sm[t >> 5] = s; sm2[t >> 5] = ss; }
    __syncthreads();
    float ts = 0.f, tss = 0.f;
#pragma unroll
    for (int i = 0; i < 8; i++) { ts += sm[i]; tss += sm2[i]; }
    const float mu   = ts * (1.0f / 1024.0f);
    const float var  = tss * (1.0f / 1024.0f) - mu * mu;
    const float istd = rsqrtf(var + 1e-5f);
    const float4 gv = ((const float4*)gg)[t];
    const float4 bv = ((const float4*)bb)[t];
    float4 ov;
    ov.x = (v0 - mu) * istd * gv.x + bv.x;
    ov.y = (v1 - mu) * istd * gv.y + bv.y;
    ov.z = (v2 - mu) * istd * gv.z + bv.z;
    ov.w = (v3 - mu) * istd * gv.w + bv.w;
    ((float4*)O)[(size_t)row * 256 + t] = ov;
    if (TOH) {
        const size_t base = (size_t)row * 512 + 2 * t;
        ((__half2*)Oh)[base]     = __halves2half2(__float2half_rn(ov.x), __float2half_rn(ov.y));
        ((__half2*)Oh)[base + 1] = __halves2half2(__float2half_rn(ov.z), __float2half_rn(ov.w));
    }
}

// ---------------- launcher ----------------
extern "C" void kernel_launch(void* const* d_in, const int* in_sizes, int n_in,
                              void* d_out, int out_size)
{
    (void)in_sizes; (void)n_in; (void)out_size;
    const float* x    = (const float*)d_in[0];
    const float* enc  = (const float*)d_in[1];
    const int*   mask = (const int*)  d_in[2];
    const float* q1W  = (const float*)d_in[3];
    const float* w1W  = (const float*)d_in[4];
    const float* o1W  = (const float*)d_in[5];
    const float* q2W  = (const float*)d_in[6];
    const float* w2W  = (const float*)d_in[7];
    const float* o2W  = (const float*)d_in[8];
    const float* ffW1 = (const float*)d_in[9];
    const float* ffb1 = (const float*)d_in[10];
    const float* ffW2 = (const float*)d_in[11];
    const float* ffb2 = (const float*)d_in[12];
    const float* g1   = (const float*)d_in[13];
    const float* b1   = (const float*)d_in[14];
    const float* g2   = (const float*)d_in[15];
    const float* b2   = (const float*)d_in[16];
    const float* g3   = (const float*)d_in[17];
    const float* b3   = (const float*)d_in[18];

    float *pq, *pk, *pt0, *pt1, *px1, *px2, *phd;
    half *hid, *wpool;
    cudaGetSymbolAddress((void**)&pq,    g_q);
    cudaGetSymbolAddress((void**)&pk,    g_k);
    cudaGetSymbolAddress((void**)&pt0,   g_t0);
    cudaGetSymbolAddress((void**)&pt1,   g_t1);
    cudaGetSymbolAddress((void**)&px1,   g_x1);
    cudaGetSymbolAddress((void**)&px2,   g_x2);
    cudaGetSymbolAddress((void**)&phd,   g_h);
    cudaGetSymbolAddress((void**)&hid,   g_ah);
    cudaGetSymbolAddress((void**)&wpool, g_w);

    half* actH = (half*)phd;
    half* encH = (half*)pt0;
    half* qh   = (half*)pq;
    half* kh1  = (half*)pk;
    half* kh2  = kh1 + (size_t)NHEADS * ROWS * HD;
    const size_t M1 = 1024 * 1024;
    half* wQ1 = wpool;          half* wK1 = wpool + M1;
    half* wO1 = wpool + 2*M1;   half* wQ2 = wpool + 3*M1;
    half* wK2 = wpool + 4*M1;   half* wO2 = wpool + 5*M1;
    half* wF1 = wpool + 6*M1;   half* wF2 = wpool + 10*M1;

    // one-time handles (created on the uncaptured correctness call)
    static cudaStream_t s2 = nullptr, s3 = nullptr;
    static cudaEvent_t evFork, evW1, evO1, evQ2, evO2, evF1, evF2, evK2, evAct, evK1;
    if (!s2) {
        cudaStreamCreateWithFlags(&s2, cudaStreamNonBlocking);
        cudaStreamCreateWithFlags(&s3, cudaStreamNonBlocking);
        cudaEventCreateWithFlags(&evFork, cudaEventDisableTiming);
        cudaEventCreateWithFlags(&evW1,   cudaEventDisableTiming);
        cudaEventCreateWithFlags(&evO1,   cudaEventDisableTiming);
        cudaEventCreateWithFlags(&evQ2,   cudaEventDisableTiming);
        cudaEventCreateWithFlags(&evO2,   cudaEventDisableTiming);
        cudaEventCreateWithFlags(&evF1,   cudaEventDisableTiming);
        cudaEventCreateWithFlags(&evF2,   cudaEventDisableTiming);
        cudaEventCreateWithFlags(&evK2,   cudaEventDisableTiming);
        cudaEventCreateWithFlags(&evAct,  cudaEventDisableTiming);
        cudaEventCreateWithFlags(&evK1,   cudaEventDisableTiming);
        cudaFuncSetAttribute(mma_gemm<0>, cudaFuncAttributeMaxDynamicSharedMemorySize, GEMM_SMEM);
        cudaFuncSetAttribute(mma_gemm<1>, cudaFuncAttributeMaxDynamicSharedMemorySize, GEMM_SMEM);
        cudaFuncSetAttribute(mma_gemm<2>, cudaFuncAttributeMaxDynamicSharedMemorySize, GEMM_SMEM);
        cudaFuncSetAttribute(mma_gemm<3>, cudaFuncAttributeMaxDynamicSharedMemorySize, GEMM_SMEM);
        cudaFuncSetAttribute(flash_mma<false>, cudaFuncAttributeMaxDynamicSharedMemorySize, FLASH_SMEM);
        cudaFuncSetAttribute(flash_mma<true>,  cudaFuncAttributeMaxDynamicSharedMemorySize, FLASH_SMEM);
    }

    const dim3 gP(D_MODEL / 128, ROWS / 128);   // (8, 32)
    const dim3 gF1g(MLP / 128, ROWS / 128);     // (32, 32)
    const dim3 gAttn(SEQ / 128, NHEADS, 2);     // (16, 16, 2)
    const dim3 tW(D_MODEL / 32, D_MODEL / 32);
    const dim3 tW1(MLP / 32, D_MODEL / 32);
    const dim3 tW2(D_MODEL / 32, MLP / 32);
    const int n4_act = ROWS * D_MODEL / 4;

    // ---- fork side stream s2: weight conversions + cross-attn K chain (R12 order) ----
    cudaEventRecord(evFork, 0);
    cudaStreamWaitEvent(s2, evFork, 0);
    tsplit<1><<<tW, 256, 0, s2>>>(w1W, wK1, D_MODEL, D_MODEL);
    cudaEventRecord(evW1, s2);
    tsplit<2><<<tW, 256, 0, s2>>>(o1W, wO1, D_MODEL, D_MODEL);
    cudaEventRecord(evO1, s2);
    tsplit<1><<<tW, 256, 0, s2>>>(q2W, wQ2, D_MODEL, D_MODEL);
    cudaEventRecord(evQ2, s2);
    tsplit<2><<<tW, 256, 0, s2>>>(o2W, wO2, D_MODEL, D_MODEL);
    cudaEventRecord(evO2, s2);
    tsplit<0><<<tW1, 256, 0, s2>>>(ffW1, wF1, D_MODEL, MLP);
    cudaEventRecord(evF1, s2);
    tsplit<0><<<tW2, 256, 0, s2>>>(ffW2, wF2, MLP, D_MODEL);
    cudaEventRecord(evF2, s2);
    tohalf<<<(n4_act + 255) / 256, 256, 0, s2>>>(enc, encH, n4_act);
    tsplit<1><<<tW, 256, 0, s2>>>(w2W, wK2, D_MODEL, D_MODEL);
    mma_gemm<1><<<gP, 256, GEMM_SMEM, s2>>>(encH, wK2, nullptr, nullptr, kh2, D_MODEL, D_MODEL);
    cudaEventRecord(evK2, s2);

    // ---- main chain: self-attention; K1 proj concurrent on s3 ----
    tohalf<<<(n4_act + 255) / 256, 256>>>(x, actH, n4_act);
    tsplit<1><<<tW, 256>>>(q1W, wQ1, D_MODEL, D_MODEL);
    cudaEventRecord(evAct, 0);
    cudaStreamWaitEvent(s3, evAct, 0);
    cudaStreamWaitEvent(s3, evW1, 0);
    mma_gemm<1><<<gP, 256, GEMM_SMEM, s3>>>(actH, wK1, nullptr, nullptr, kh1, D_MODEL, D_MODEL);
    cudaEventRecord(evK1, s3);
    mma_gemm<1><<<gP, 256, GEMM_SMEM>>>(actH, wQ1, nullptr, nullptr, qh, D_MODEL, D_MODEL);
    cudaStreamWaitEvent(0, evK1, 0);
    flash_mma<false><<<gAttn, 256, FLASH_SMEM>>>(qh, kh1, nullptr, actH);
    cudaStreamWaitEvent(0, evO1, 0);
    mma_gemm<0><<<gP, 256, GEMM_SMEM>>>(actH, wO1, nullptr, pt1, nullptr, D_MODEL, D_MODEL);
    add_ln_kernel<true><<<ROWS, 256>>>(x, pt1, g1, b1, px1, actH);

    // ---- cross-attention (masked) ----
    cudaStreamWaitEvent(0, evQ2, 0);
    mma_gemm<1><<<gP, 256, GEMM_SMEM>>>(actH, wQ2, nullptr, nullptr, qh, D_MODEL, D_MODEL);
    cudaStreamWaitEvent(0, evK2, 0);
    flash_mma<true><<<gAttn, 256, FLASH_SMEM>>>(qh, kh2, mask, actH);
    cudaStreamWaitEvent(0, evO2, 0);
    mma_gemm<0><<<gP, 256, GEMM_SMEM>>>(actH, wO2, nullptr, pt1, nullptr, D_MODEL, D_MODEL);
    add_ln_kernel<true><<<ROWS, 256>>>(px1, pt1, g2, b2, px2, actH);

    // ---- feed-forward ----
    cudaStreamWaitEvent(0, evF1, 0);
    mma_gemm<3><<<gF1g, 256, GEMM_SMEM>>>(actH, wF1, ffb1, nullptr, hid, MLP, D_MODEL);
    cudaStreamWaitEvent(0, evF2, 0);
    mma_gemm<2><<<gP, 256, GEMM_SMEM>>>(hid, wF2, ffb2, pt1, nullptr, D_MODEL, MLP);
    add_ln_kernel<false><<<ROWS, 256>>>(px2, pt1, g3, b3, (float*)d_out, nullptr);
}

// round 15
// speedup vs baseline: 1.5649x; 1.0322x over previous
#include <cuda_runtime.h>
#include <cuda_fp16.h>
#include <math.h>
#include <stdint.h>

#define D_MODEL 1024
#define NHEADS  16
#define HD      64
#define SEQ     2048
#define ROWS    4096   // B * SEQ
#define MLP     4096

// ---------------- scratch (static device memory; no allocs) ----------------
__device__ float g_q [NHEADS * ROWS * HD];     // 16 MB -> qh half pool
__device__ float g_k [NHEADS * ROWS * HD];     // 16 MB -> kh1 + kh2 half pools
__device__ float g_t0[ROWS * D_MODEL];         // enc half
__device__ float g_t1[ROWS * D_MODEL];         // fp32 gemm outputs
__device__ float g_x1[ROWS * D_MODEL];
__device__ float g_x2[ROWS * D_MODEL];
__device__ float g_h [ROWS * MLP];             // act half
__device__ half  g_ah[ROWS * MLP];             // 32 MB hid (GELU out)
__device__ half  g_w [14 * 1024 * 1024];       // 28 MB weight pool

// ---------------- PTX helpers ----------------
__device__ __forceinline__ uint32_t smem_u32(const void* p) {
    uint32_t a;
    asm("{ .reg .u64 t; cvta.to.shared.u64 t, %1; cvt.u32.u64 %0, t; }" : "=r"(a) : "l"(p));
    return a;
}
__device__ __forceinline__ void cp16(uint32_t dst, const void* src) {
    asm volatile("cp.async.cg.shared.global [%0], [%1], 16;" :: "r"(dst), "l"(src));
}
__device__ __forceinline__ void cp_commit() { asm volatile("cp.async.commit_group;"); }
template <int N> __device__ __forceinline__ void cp_wait() {
    asm volatile("cp.async.wait_group %0;" :: "n"(N) : "memory");
}
__device__ __forceinline__ void ldsm4(uint32_t* r, uint32_t a) {
    asm volatile("ldmatrix.sync.aligned.m8n8.x4.shared.b16 {%0,%1,%2,%3}, [%4];"
                 : "=r"(r[0]), "=r"(r[1]), "=r"(r[2]), "=r"(r[3]) : "r"(a));
}
__device__ __forceinline__ void ldsm4t(uint32_t* r, uint32_t a) {
    asm volatile("ldmatrix.sync.aligned.m8n8.x4.trans.shared.b16 {%0,%1,%2,%3}, [%4];"
                 : "=r"(r[0]), "=r"(r[1]), "=r"(r[2]), "=r"(r[3]) : "r"(a));
}
__device__ __forceinline__ void mma16816h(float* d, const uint32_t* a, const uint32_t* b) {
    asm volatile("mma.sync.aligned.m16n8k16.row.col.f32.f16.f16.f32 "
                 "{%0,%1,%2,%3}, {%4,%5,%6,%7}, {%8,%9}, {%0,%1,%2,%3};"
                 : "+f"(d[0]), "+f"(d[1]), "+f"(d[2]), "+f"(d[3])
                 : "r"(a[0]), "r"(a[1]), "r"(a[2]), "r"(a[3]), "r"(b[0]), "r"(b[1]));
}
__device__ __forceinline__ uint32_t packh(float a, float b) {
    __half2 t = __halves2half2(__float2half_rn(a), __float2half_rn(b));
    return *(uint32_t*)&t;
}

#define SWZ(x) ((x) ^ ((((uint32_t)(x)) >> 3) & 0x70))
#define SOFF(b) ((b) * 32768u)
#define GEMM_SMEM 98304
#define FLASH_SMEM 84992   // Q 16K + K 2x32K + mask 2K + pad

// ---------------- HMMA fp16 GEMM (128x128, 3-stage, 256 thr, occ 2) -------
// EPI: 0 fp32 C; 1 single-half head-contig; 2 +bias fp32; 3 +bias+GELU half.
template <int EPI>
__global__ __launch_bounds__(256, 2)
void mma_gemm(const half* __restrict__ A, const half* __restrict__ W,
              const float* __restrict__ bias, float* __restrict__ C,
              half* __restrict__ Oh, int N, int K)
{
    extern __shared__ __align__(1024) char smem[];
    const uint32_t sb = smem_u32(smem);
    const int tid = threadIdx.x, wid = tid >> 5, lane = tid & 31;
    const int bx = blockIdx.x, by = blockIdx.y;
    const int rowA0 = by * 128, rowB0 = bx * 128;

    const int r7 = lane & 7;
    const int aRowBase = (wid & 1) * 64 + ((lane >> 3) & 1) * 8 + r7;
    const int aGranLane = lane >> 4;
    const int bRowBase = (wid >> 1) * 32 + ((lane >> 4) << 3) + r7;
    const int bGranLane = (lane >> 3) & 1;

    float acc[4][4][4];
#pragma unroll
    for (int i = 0; i < 4; i++)
#pragma unroll
        for (int j = 0; j < 4; j++)
#pragma unroll
            for (int v = 0; v < 4; v++) acc[i][j][v] = 0.f;

    const int NCH = K >> 6;

    auto load_chunk = [&](int i, int b) {
        const int k0 = i << 6;
        const uint32_t st = sb + SOFF(b);
#pragma unroll
        for (int it = 0; it < 4; it++) {
            const int c = tid + it * 256;
            const int r = c >> 3, q = c & 7;
            const uint32_t d = SWZ(r * 128 + q * 16);
            cp16(st + d,         A + (size_t)(rowA0 + r) * K + k0 + q * 8);
            cp16(st + 16384 + d, W + (size_t)(rowB0 + r) * K + k0 + q * 8);
        }
        cp_commit();
    };

    load_chunk(0, 0);
    load_chunk(1, 1);

    for (int i = 0; i < NCH; i++) {
        const int b = i % 3;
        if (i + 2 < NCH)      { load_chunk(i + 2, (i + 2) % 3); cp_wait<2>(); }
        else if (i + 1 < NCH) { cp_wait<1>(); }
        else                  { cp_wait<0>(); }
        __syncthreads();

        const uint32_t bA = sb + SOFF(b), bW = bA + 16384;
#pragma unroll
        for (int ks = 0; ks < 4; ks++) {
            const int ga = ((2 * ks + aGranLane) ^ r7) << 4;
            const int gb = ((2 * ks + bGranLane) ^ r7) << 4;
            uint32_t ah[4][4], bh[2][4];
#pragma unroll
            for (int mf = 0; mf < 4; mf++)
                ldsm4(ah[mf], bA + (uint32_t)(aRowBase + mf * 16) * 128 + ga);
#pragma unroll
            for (int ng = 0; ng < 2; ng++)
                ldsm4(bh[ng], bW + (uint32_t)(bRowBase + ng * 16) * 128 + gb);
#pragma unroll
            for (int mf = 0; mf < 4; mf++)
#pragma unroll
                for (int n8 = 0; n8 < 4; n8++)
                    mma16816h(acc[mf][n8], ah[mf], &bh[n8 >> 1][(n8 & 1) * 2]);
        }
        __syncthreads();
    }

    const int mrow0 = by * 128 + (wid & 1) * 64 + (lane >> 2);
    const int ncol0 = bx * 128 + (wid >> 1) * 32 + (lane & 3) * 2;
#pragma unroll
    for (int mf = 0; mf < 4; mf++) {
#pragma unroll
        for (int n8 = 0; n8 < 4; n8++) {
            const int c = ncol0 + n8 * 8;
#pragma unroll
            for (int half_i = 0; half_i < 2; half_i++) {
                const int r = mrow0 + mf * 16 + half_i * 8;
                float v0 = acc[mf][n8][half_i * 2], v1 = acc[mf][n8][half_i * 2 + 1];
                if (EPI == 2 || EPI == 3) { v0 += bias[c]; v1 += bias[c + 1]; }
                if (EPI == 3) {
                    v0 = 0.5f * v0 * (1.0f + erff(v0 * 0.70710678118654752f));
                    v1 = 0.5f * v1 * (1.0f + erff(v1 * 0.70710678118654752f));
                }
                if (EPI == 1) {
                    const size_t i0 = (size_t)(c >> 6) * (ROWS * HD) + (size_t)r * HD + (c & 63);
                    *(__half2*)(Oh + i0) = __halves2half2(__float2half_rn(v0), __float2half_rn(v1));
                } else if (EPI == 3) {
                    const size_t i0 = (size_t)r * N + c;
                    *(__half2*)(Oh + i0) = __halves2half2(__float2half_rn(v0), __float2half_rn(v1));
                } else {
                    *(float2*)(C + (size_t)r * N + c) = make_float2(v0, v1);
                }
            }
        }
    }
}

// ---------------- conversion kernels ----------------
__global__ __launch_bounds__(256)
void tohalf(const float* __restrict__ in, half* __restrict__ hi, int n4)
{
    const int i = blockIdx.x * 256 + threadIdx.x;
    if (i >= n4) return;
    const float4 v = ((const float4*)in)[i];
    ((__half2*)hi)[2 * i]     = __halves2half2(__float2half_rn(v.x), __float2half_rn(v.y));
    ((__half2*)hi)[2 * i + 1] = __halves2half2(__float2half_rn(v.z), __float2half_rn(v.w));
}

template <int PERM>
__global__ __launch_bounds__(256)
void tsplit(const float* __restrict__ W, half* __restrict__ th, int K, int N)
{
    __shared__ float t[32][33];
    const int n0 = blockIdx.x * 32, k0 = blockIdx.y * 32;
    const int tx = threadIdx.x & 31, ty = threadIdx.x >> 5;
#pragma unroll
    for (int j = 0; j < 32; j += 8)
        t[ty + j][tx] = W[(size_t)(k0 + ty + j) * N + n0 + tx];
    __syncthreads();
#pragma unroll
    for (int j = 0; j < 32; j += 8) {
        const float v = t[tx][ty + j];
        const int ocol = n0 + ty + j;
        const int orow = k0 + tx;
        const int srow = (PERM & 1) ? ((ocol & 15) * 64 + (ocol >> 4)) : ocol;
        const int scol = (PERM & 2) ? ((orow & 15) * 64 + (orow >> 4)) : orow;
        th[(size_t)srow * K + scol] = __float2half_rn(v);
    }
}

// ---------------- HMMA fp16 flash attention (values == K) ----------------
// kv super-tile 256 (4 x 64 sub-steps), double-buffered.
template <bool MASKED>
__global__ __launch_bounds__(256, 2)
void flash_mma(const half* __restrict__ Qf, const half* __restrict__ Kf,
               const int* __restrict__ mask, half* __restrict__ Oh)
{
    extern __shared__ __align__(1024) char smem[];
    const uint32_t sb = smem_u32(smem);
    const uint32_t sQ = sb;                      // 16K
    const uint32_t sK = sb + 16384;              // buf b @ +b*32768 (256 rows x 128B)
    float* sMf = (float*)(smem + 81920);         // [2][256]
    const int tid = threadIdx.x, wid = tid >> 5, lane = tid & 31;
    const int r7 = lane & 7;
    const int head = blockIdx.y, bat = blockIdx.z;
    const int qr0 = blockIdx.x * 128;
    const size_t hoff = (size_t)head * ROWS * HD;
    const half* gQ = Qf + hoff + (size_t)(bat * SEQ + qr0) * HD;
    const half* gK = Kf + hoff + (size_t)bat * SEQ * HD;

#pragma unroll
    for (int it = 0; it < 4; it++) {
        const int c = tid + it * 256;
        const int r = c >> 3, q = c & 7;
        cp16(sQ + SWZ(r * 128 + q * 16), gQ + (size_t)r * HD + q * 8);
    }
    cp_commit();

    auto load_k = [&](int mt2) {
        const uint32_t kb = sK + (mt2 & 1) * 32768;
#pragma unroll
        for (int it = 0; it < 8; it++) {
            const int c = tid + it * 256;          // 0..2047
            const int r = c >> 3, q = c & 7;       // r 0..255
            cp16(kb + SWZ(r * 128 + q * 16), gK + (size_t)(mt2 * 256 + r) * HD + q * 8);
        }
        if (MASKED)
            sMf[(mt2 & 1) * 256 + tid] = (float)mask[bat * SEQ + mt2 * 256 + tid];
        cp_commit();
    };
    load_k(0);

    uint32_t aQ[4][4];
    cp_wait<1>();
    __syncthreads();
    {
        const int row = wid * 16 + ((lane >> 3) & 1) * 8 + r7;
        const int g = lane >> 4;
#pragma unroll
        for (int ks = 0; ks < 4; ks++)
            ldsm4(aQ[ks], sQ + (uint32_t)row * 128 + ((((ks << 1) + g) ^ r7) << 4));
    }

    float o[8][4];
#pragma unroll
    for (int j = 0; j < 8; j++) { o[j][0] = o[j][1] = o[j][2] = o[j][3] = 0.f; }
    float lsum0 = 0.f, lsum1 = 0.f;

    const int sRowB = ((lane >> 4) << 3) + r7;
    const int sGran = (lane >> 3) & 1;
    const int tRowB = ((lane >> 3) & 1) * 8 + r7;
    const int tGran = lane >> 4;

    for (int mt2 = 0; mt2 < SEQ / 256; mt2++) {
        const uint32_t kb = sK + (mt2 & 1) * 32768;
        if (mt2 + 1 < SEQ / 256) { load_k(mt2 + 1); cp_wait<1>(); }
        else                     { cp_wait<0>(); }
        __syncthreads();

#pragma unroll
        for (int sub = 0; sub < 4; sub++) {
            const uint32_t ks_base = kb + sub * 8192;   // 64 rows x 128B
            float s[8][4];
#pragma unroll
            for (int j = 0; j < 8; j++) { s[j][0] = s[j][1] = s[j][2] = s[j][3] = 0.f; }
#pragma unroll
            for (int ks = 0; ks < 4; ks++) {
                const uint32_t gg = ((((ks << 1) + sGran) ^ r7) << 4);
#pragma unroll
                for (int ng = 0; ng < 4; ng++) {
                    uint32_t bh[4];
                    ldsm4(bh, ks_base + (uint32_t)(ng * 16 + sRowB) * 128 + gg);
                    mma16816h(s[2 * ng],     aQ[ks], bh);
                    mma16816h(s[2 * ng + 1], aQ[ks], bh + 2);
                }
            }

            uint32_t ph[8][2];
#pragma unroll
            for (int j = 0; j < 8; j++) {
                if (MASKED) {
                    const int c0 = (mt2 & 1) * 256 + sub * 64 + j * 8 + (lane & 3) * 2;
                    if (sMf[c0]     != 0.f) { s[j][0] = -1e9f; s[j][2] = -1e9f; }
                    if (sMf[c0 + 1] != 0.f) { s[j][1] = -1e9f; s[j][3] = -1e9f; }
                }
                const float p0 = __expf(s[j][0] * 0.125f);
                const float p1 = __expf(s[j][1] * 0.125f);
                const float p2 = __expf(s[j][2] * 0.125f);
                const float p3 = __expf(s[j][3] * 0.125f);
                lsum0 += p0 + p1; lsum1 += p2 + p3;
                ph[j][0] = packh(p0, p1);
                ph[j][1] = packh(p2, p3);
            }

#pragma unroll
            for (int m16 = 0; m16 < 4; m16++) {
                uint32_t ah[4] = {ph[2 * m16][0], ph[2 * m16][1], ph[2 * m16 + 1][0], ph[2 * m16 + 1][1]};
#pragma unroll
                for (int dt = 0; dt < 4; dt++) {
                    uint32_t bh[4];
                    ldsm4t(bh, ks_base + (uint32_t)(m16 * 16 + tRowB) * 128 +
                               ((((dt << 1) + tGran) ^ r7) << 4));
                    mma16816h(o[2 * dt],     ah, bh);
                    mma16816h(o[2 * dt + 1], ah, bh + 2);
                }
            }
        }
        __syncthreads();
    }

    lsum0 += __shfl_xor_sync(0xffffffffu, lsum0, 1);
    lsum0 += __shfl_xor_sync(0xffffffffu, lsum0, 2);
    lsum1 += __shfl_xor_sync(0xffffffffu, lsum1, 1);
    lsum1 += __shfl_xor_sync(0xffffffffu, lsum1, 2);
    const float inv0 = 1.0f / lsum0, inv1 = 1.0f / lsum1;

    const int grow0 = bat * SEQ + qr0 + wid * 16 + (lane >> 2);
#pragma unroll
    for (int j = 0; j < 8; j++) {
        const int d0 = j * 8 + (lane & 3) * 2;
        const size_t b0 = (size_t)grow0 * D_MODEL + head * 64 + d0;
        const size_t b1 = (size_t)(grow0 + 8) * D_MODEL + head * 64 + d0;
        *(__half2*)(Oh + b0) = __halves2half2(
            __float2half_rn(o[j][0] * inv0), __float2half_rn(o[j][1] * inv0));
        *(__half2*)(Oh + b1) = __halves2half2(
            __float2half_rn(o[j][2] * inv1), __float2half_rn(o[j][3] * inv1));
    }
}

// ---------------- fused residual + LayerNorm (+ optional half out) --------
template <bool TOH>
__global__ __launch_bounds__(256)
void add_ln_kernel(const float* __restrict__ X, const float* __restrict__ R,
                   const float* __restrict__ gg, const float* __restrict__ bb,
                   float* __restrict__ O, half* __restrict__ Oh)
{
    const int row = blockIdx.x, t = threadIdx.x;
    const float4 xv = ((const float4*)X)[(size_t)row * 256 + t];
    const float4 rv = ((const float4*)R)[(size_t)row * 256 + t];
    const float v0 = xv.x + rv.x, v1 = xv.y + rv.y, v2 = xv.z + rv.z, v3 = xv.w + rv.w;
    float s  = v0 + v1 + v2 + v3;
    float ss = v0 * v0 + v1 * v1 + v2 * v2 + v3 * v3;
#pragma unroll
    for (int o = 16; o; o >>= 1) {
        s  += __shfl_xor_sync(0xffffffffu, s,  o);
        ss += __shfl_xor_sync(0xffffffffu, ss, o);
    }
    __shared__ float sm[8], sm2[8];
    if ((t & 31) == 0) { sm[t >> 5] = s; sm2[t >> 5] = ss; }
    __syncthreads();
    float ts = 0.f, tss = 0.f;
#pragma unroll
    for (int i = 0; i < 8; i++) { ts += sm[i]; tss += sm2[i]; }
    const float mu   = ts * (1.0f / 1024.0f);
    const float var  = tss * (1.0f / 1024.0f) - mu * mu;
    const float istd = rsqrtf(var + 1e-5f);
    const float4 gv = ((const float4*)gg)[t];
    const float4 bv = ((const float4*)bb)[t];
    float4 ov;
    ov.x = (v0 - mu) * istd * gv.x + bv.x;
    ov.y = (v1 - mu) * istd * gv.y + bv.y;
    ov.z = (v2 - mu) * istd * gv.z + bv.z;
    ov.w = (v3 - mu) * istd * gv.w + bv.w;
    ((float4*)O)[(size_t)row * 256 + t] = ov;
    if (TOH) {
        const size_t base = (size_t)row * 512 + 2 * t;
        ((__half2*)Oh)[base]     = __halves2half2(__float2half_rn(ov.x), __float2half_rn(ov.y));
        ((__half2*)Oh)[base + 1] = __halves2half2(__float2half_rn(ov.z), __float2half_rn(ov.w));
    }
}

// ---------------- launcher ----------------
extern "C" void kernel_launch(void* const* d_in, const int* in_sizes, int n_in,
                              void* d_out, int out_size)
{
    (void)in_sizes; (void)n_in; (void)out_size;
    const float* x    = (const float*)d_in[0];
    const float* enc  = (const float*)d_in[1];
    const int*   mask = (const int*)  d_in[2];
    const float* q1W  = (const float*)d_in[3];
    const float* w1W  = (const float*)d_in[4];
    const float* o1W  = (const float*)d_in[5];
    const float* q2W  = (const float*)d_in[6];
    const float* w2W  = (const float*)d_in[7];
    const float* o2W  = (const float*)d_in[8];
    const float* ffW1 = (const float*)d_in[9];
    const float* ffb1 = (const float*)d_in[10];
    const float* ffW2 = (const float*)d_in[11];
    const float* ffb2 = (const float*)d_in[12];
    const float* g1   = (const float*)d_in[13];
    const float* b1   = (const float*)d_in[14];
    const float* g2   = (const float*)d_in[15];
    const float* b2   = (const float*)d_in[16];
    const float* g3   = (const float*)d_in[17];
    const float* b3   = (const float*)d_in[18];

    float *pq, *pk, *pt0, *pt1, *px1, *px2, *phd;
    half *hid, *wpool;
    cudaGetSymbolAddress((void**)&pq,    g_q);
    cudaGetSymbolAddress((void**)&pk,    g_k);
    cudaGetSymbolAddress((void**)&pt0,   g_t0);
    cudaGetSymbolAddress((void**)&pt1,   g_t1);
    cudaGetSymbolAddress((void**)&px1,   g_x1);
    cudaGetSymbolAddress((void**)&px2,   g_x2);
    cudaGetSymbolAddress((void**)&phd,   g_h);
    cudaGetSymbolAddress((void**)&hid,   g_ah);
    cudaGetSymbolAddress((void**)&wpool, g_w);

    half* actH = (half*)phd;
    half* encH = (half*)pt0;
    half* qh   = (half*)pq;
    half* kh1  = (half*)pk;
    half* kh2  = kh1 + (size_t)NHEADS * ROWS * HD;
    const size_t M1 = 1024 * 1024;
    half* wQ1 = wpool;          half* wK1 = wpool + M1;
    half* wO1 = wpool + 2*M1;   half* wQ2 = wpool + 3*M1;
    half* wK2 = wpool + 4*M1;   half* wO2 = wpool + 5*M1;
    half* wF1 = wpool + 6*M1;   half* wF2 = wpool + 10*M1;

    static cudaStream_t s2 = nullptr, s3 = nullptr;
    static cudaEvent_t evFork, evW1, evO1, evQ2, evO2, evF1, evF2, evK2, evAct, evK1,
                       evLn2, evFFb;
    if (!s2) {
        cudaStreamCreateWithFlags(&s2, cudaStreamNonBlocking);
        cudaStreamCreateWithFlags(&s3, cudaStreamNonBlocking);
        cudaEventCreateWithFlags(&evFork, cudaEventDisableTiming);
        cudaEventCreateWithFlags(&evW1,   cudaEventDisableTiming);
        cudaEventCreateWithFlags(&evO1,   cudaEventDisableTiming);
        cudaEventCreateWithFlags(&evQ2,   cudaEventDisableTiming);
        cudaEventCreateWithFlags(&evO2,   cudaEventDisableTiming);
        cudaEventCreateWithFlags(&evF1,   cudaEventDisableTiming);
        cudaEventCreateWithFlags(&evF2,   cudaEventDisableTiming);
        cudaEventCreateWithFlags(&evK2,   cudaEventDisableTiming);
        cudaEventCreateWithFlags(&evAct,  cudaEventDisableTiming);
        cudaEventCreateWithFlags(&evK1,   cudaEventDisableTiming);
        cudaEventCreateWithFlags(&evLn2,  cudaEventDisableTiming);
        cudaEventCreateWithFlags(&evFFb,  cudaEventDisableTiming);
        cudaFuncSetAttribute(mma_gemm<0>, cudaFuncAttributeMaxDynamicSharedMemorySize, GEMM_SMEM);
        cudaFuncSetAttribute(mma_gemm<1>, cudaFuncAttributeMaxDynamicSharedMemorySize, GEMM_SMEM);
        cudaFuncSetAttribute(mma_gemm<2>, cudaFuncAttributeMaxDynamicSharedMemorySize, GEMM_SMEM);
        cudaFuncSetAttribute(mma_gemm<3>, cudaFuncAttributeMaxDynamicSharedMemorySize, GEMM_SMEM);
        cudaFuncSetAttribute(flash_mma<false>, cudaFuncAttributeMaxDynamicSharedMemorySize, FLASH_SMEM);
        cudaFuncSetAttribute(flash_mma<true>,  cudaFuncAttributeMaxDynamicSharedMemorySize, FLASH_SMEM);
    }

    const dim3 gP(D_MODEL / 128, ROWS / 128);    // (8, 32)
    const dim3 gPh(D_MODEL / 128, ROWS / 256);   // (8, 16)  row-half
    const dim3 gF1g(MLP / 128, ROWS / 128);      // (32, 32)
    const dim3 gF1h(MLP / 128, ROWS / 256);      // (32, 16) row-half
    const dim3 gAttn(SEQ / 128, NHEADS, 2);
    const dim3 tW(D_MODEL / 32, D_MODEL / 32);
    const dim3 tW1(MLP / 32, D_MODEL / 32);
    const dim3 tW2(D_MODEL / 32, MLP / 32);
    const int n4_act = ROWS * D_MODEL / 4;
    const size_t HROWS = ROWS / 2;                    // 2048

    // ---- fork side stream s2: weight conversions + cross-attn K chain ----
    cudaEventRecord(evFork, 0);
    cudaStreamWaitEvent(s2, evFork, 0);
    tsplit<1><<<tW, 256, 0, s2>>>(w1W, wK1, D_MODEL, D_MODEL);
    cudaEventRecord(evW1, s2);
    tsplit<2><<<tW, 256, 0, s2>>>(o1W, wO1, D_MODEL, D_MODEL);
    cudaEventRecord(evO1, s2);
    tsplit<1><<<tW, 256, 0, s2>>>(q2W, wQ2, D_MODEL, D_MODEL);
    cudaEventRecord(evQ2, s2);
    tsplit<2><<<tW, 256, 0, s2>>>(o2W, wO2, D_MODEL, D_MODEL);
    cudaEventRecord(evO2, s2);
    tsplit<0><<<tW1, 256, 0, s2>>>(ffW1, wF1, D_MODEL, MLP);
    cudaEventRecord(evF1, s2);
    tsplit<0><<<tW2, 256, 0, s2>>>(ffW2, wF2, MLP, D_MODEL);
    cudaEventRecord(evF2, s2);
    tohalf<<<(n4_act + 255) / 256, 256, 0, s2>>>(enc, encH, n4_act);
    tsplit<1><<<tW, 256, 0, s2>>>(w2W, wK2, D_MODEL, D_MODEL);
    mma_gemm<1><<<gP, 256, GEMM_SMEM, s2>>>(encH, wK2, nullptr, nullptr, kh2, D_MODEL, D_MODEL);
    cudaEventRecord(evK2, s2);

    // ---- main chain: self-attention; K1 proj concurrent on s3 ----
    tohalf<<<(n4_act + 255) / 256, 256>>>(x, actH, n4_act);
    tsplit<1><<<tW, 256>>>(q1W, wQ1, D_MODEL, D_MODEL);
    cudaEventRecord(evAct, 0);
    cudaStreamWaitEvent(s3, evAct, 0);
    cudaStreamWaitEvent(s3, evW1, 0);
    mma_gemm<1><<<gP, 256, GEMM_SMEM, s3>>>(actH, wK1, nullptr, nullptr, kh1, D_MODEL, D_MODEL);
    cudaEventRecord(evK1, s3);
    mma_gemm<1><<<gP, 256, GEMM_SMEM>>>(actH, wQ1, nullptr, nullptr, qh, D_MODEL, D_MODEL);
    cudaStreamWaitEvent(0, evK1, 0);
    flash_mma<false><<<gAttn, 256, FLASH_SMEM>>>(qh, kh1, nullptr, actH);
    cudaStreamWaitEvent(0, evO1, 0);
    mma_gemm<0><<<gP, 256, GEMM_SMEM>>>(actH, wO1, nullptr, pt1, nullptr, D_MODEL, D_MODEL);
    add_ln_kernel<true><<<ROWS, 256>>>(x, pt1, g1, b1, px1, actH);

    // ---- cross-attention (masked) ----
    cudaStreamWaitEvent(0, evQ2, 0);
    mma_gemm<1><<<gP, 256, GEMM_SMEM>>>(actH, wQ2, nullptr, nullptr, qh, D_MODEL, D_MODEL);
    cudaStreamWaitEvent(0, evK2, 0);
    flash_mma<true><<<gAttn, 256, FLASH_SMEM>>>(qh, kh2, mask, actH);
    cudaStreamWaitEvent(0, evO2, 0);
    mma_gemm<0><<<gP, 256, GEMM_SMEM>>>(actH, wO2, nullptr, pt1, nullptr, D_MODEL, D_MODEL);
    add_ln_kernel<true><<<ROWS, 256>>>(px1, pt1, g2, b2, px2, actH);
    cudaEventRecord(evLn2, 0);

    // ---- feed-forward: row-split pipeline (main = rows 0-2047, s3 = 2048-4095) ----
    cudaStreamWaitEvent(s3, evLn2, 0);
    cudaStreamWaitEvent(s3, evF1, 0);
    mma_gemm<3><<<gF1h, 256, GEMM_SMEM, s3>>>(actH + HROWS * D_MODEL, wF1, ffb1, nullptr,
                                              hid + HROWS * MLP, MLP, D_MODEL);
    cudaStreamWaitEvent(s3, evF2, 0);
    mma_gemm<2><<<gPh, 256, GEMM_SMEM, s3>>>(hid + HROWS * MLP, wF2, ffb2,
                                             pt1 + HROWS * D_MODEL, nullptr, D_MODEL, MLP);
    add_ln_kernel<false><<<ROWS / 2, 256, 0, s3>>>(px2 + HROWS * D_MODEL, pt1 + HROWS * D_MODEL,
                                                   g3, b3, (float*)d_out + HROWS * D_MODEL, nullptr);
    cudaEventRecord(evFFb, s3);

    cudaStreamWaitEvent(0, evF1, 0);
    mma_gemm<3><<<gF1h, 256, GEMM_SMEM>>>(actH, wF1, ffb1, nullptr, hid, MLP, D_MODEL);
    cudaStreamWaitEvent(0, evF2, 0);
    mma_gemm<2><<<gPh, 256, GEMM_SMEM>>>(hid, wF2, ffb2, pt1, nullptr, D_MODEL, MLP);
    add_ln_kernel<false><<<ROWS / 2, 256>>>(px2, pt1, g3, b3, (float*)d_out, nullptr);
    cudaStreamWaitEvent(0, evFFb, 0);
}

// round 16
// speedup vs baseline: 1.6012x; 1.0232x over previous
#include <cuda_runtime.h>
#include <cuda_fp16.h>
#include <math.h>
#include <stdint.h>

#define D_MODEL 1024
#define NHEADS  16
#define HD      64
#define SEQ     2048
#define ROWS    4096   // B * SEQ
#define MLP     4096

// ---------------- scratch (static device memory; no allocs) ----------------
__device__ float g_q [NHEADS * ROWS * HD];     // 16 MB -> qh half pool
__device__ float g_k [NHEADS * ROWS * HD];     // 16 MB -> kh1 + kh2 half pools
__device__ float g_t0[ROWS * D_MODEL];         // enc half
__device__ float g_t1[ROWS * D_MODEL];         // fp32 gemm outputs
__device__ float g_x1[ROWS * D_MODEL];
__device__ float g_x2[ROWS * D_MODEL];
__device__ float g_h [ROWS * MLP];             // act half
__device__ half  g_ah[ROWS * MLP];             // 32 MB hid (GELU out)
__device__ half  g_w [14 * 1024 * 1024];       // 28 MB weight pool

// ---------------- PTX helpers ----------------
__device__ __forceinline__ uint32_t smem_u32(const void* p) {
    uint32_t a;
    asm("{ .reg .u64 t; cvta.to.shared.u64 t, %1; cvt.u32.u64 %0, t; }" : "=r"(a) : "l"(p));
    return a;
}
__device__ __forceinline__ void cp16(uint32_t dst, const void* src) {
    asm volatile("cp.async.cg.shared.global [%0], [%1], 16;" :: "r"(dst), "l"(src));
}
__device__ __forceinline__ void cp_commit() { asm volatile("cp.async.commit_group;"); }
template <int N> __device__ __forceinline__ void cp_wait() {
    asm volatile("cp.async.wait_group %0;" :: "n"(N) : "memory");
}
__device__ __forceinline__ void ldsm4(uint32_t* r, uint32_t a) {
    asm volatile("ldmatrix.sync.aligned.m8n8.x4.shared.b16 {%0,%1,%2,%3}, [%4];"
                 : "=r"(r[0]), "=r"(r[1]), "=r"(r[2]), "=r"(r[3]) : "r"(a));
}
__device__ __forceinline__ void ldsm4t(uint32_t* r, uint32_t a) {
    asm volatile("ldmatrix.sync.aligned.m8n8.x4.trans.shared.b16 {%0,%1,%2,%3}, [%4];"
                 : "=r"(r[0]), "=r"(r[1]), "=r"(r[2]), "=r"(r[3]) : "r"(a));
}
__device__ __forceinline__ void mma16816h(float* d, const uint32_t* a, const uint32_t* b) {
    asm volatile("mma.sync.aligned.m16n8k16.row.col.f32.f16.f16.f32 "
                 "{%0,%1,%2,%3}, {%4,%5,%6,%7}, {%8,%9}, {%0,%1,%2,%3};"
                 : "+f"(d[0]), "+f"(d[1]), "+f"(d[2]), "+f"(d[3])
                 : "r"(a[0]), "r"(a[1]), "r"(a[2]), "r"(a[3]), "r"(b[0]), "r"(b[1]));
}
__device__ __forceinline__ uint32_t packh(float a, float b) {
    __half2 t = __halves2half2(__float2half_rn(a), __float2half_rn(b));
    return *(uint32_t*)&t;
}

#define SWZ(x) ((x) ^ ((((uint32_t)(x)) >> 3) & 0x70))
#define SOFF(b) ((b) * 32768u)
#define GEMM_SMEM 98304
#define FLASH_SMEM 84992   // Q 16K + K 2x32K + mask 2K + pad

// ---------------- HMMA fp16 GEMM (128x128, 3-stage, 256 thr, occ 2) -------
// EPI: 0 fp32 C; 1 single-half head-contig; 2 +bias fp32; 3 +bias+GELU half.
template <int EPI>
__global__ __launch_bounds__(256, 2)
void mma_gemm(const half* __restrict__ A, const half* __restrict__ W,
              const float* __restrict__ bias, float* __restrict__ C,
              half* __restrict__ Oh, int N, int K)
{
    extern __shared__ __align__(1024) char smem[];
    const uint32_t sb = smem_u32(smem);
    const int tid = threadIdx.x, wid = tid >> 5, lane = tid & 31;
    const int bx = blockIdx.x, by = blockIdx.y;
    const int rowA0 = by * 128, rowB0 = bx * 128;

    const int r7 = lane & 7;
    const int aRowBase = (wid & 1) * 64 + ((lane >> 3) & 1) * 8 + r7;
    const int aGranLane = lane >> 4;
    const int bRowBase = (wid >> 1) * 32 + ((lane >> 4) << 3) + r7;
    const int bGranLane = (lane >> 3) & 1;

    float acc[4][4][4];
#pragma unroll
    for (int i = 0; i < 4; i++)
#pragma unroll
        for (int j = 0; j < 4; j++)
#pragma unroll
            for (int v = 0; v < 4; v++) acc[i][j][v] = 0.f;

    const int NCH = K >> 6;

    auto load_chunk = [&](int i, int b) {
        const int k0 = i << 6;
        const uint32_t st = sb + SOFF(b);
#pragma unroll
        for (int it = 0; it < 4; it++) {
            const int c = tid + it * 256;
            const int r = c >> 3, q = c & 7;
            const uint32_t d = SWZ(r * 128 + q * 16);
            cp16(st + d,         A + (size_t)(rowA0 + r) * K + k0 + q * 8);
            cp16(st + 16384 + d, W + (size_t)(rowB0 + r) * K + k0 + q * 8);
        }
        cp_commit();
    };

    load_chunk(0, 0);
    load_chunk(1, 1);

    for (int i = 0; i < NCH; i++) {
        const int b = i % 3;
        if (i + 2 < NCH)      { load_chunk(i + 2, (i + 2) % 3); cp_wait<2>(); }
        else if (i + 1 < NCH) { cp_wait<1>(); }
        else                  { cp_wait<0>(); }
        __syncthreads();

        const uint32_t bA = sb + SOFF(b), bW = bA + 16384;
#pragma unroll
        for (int ks = 0; ks < 4; ks++) {
            const int ga = ((2 * ks + aGranLane) ^ r7) << 4;
            const int gb = ((2 * ks + bGranLane) ^ r7) << 4;
            uint32_t ah[4][4], bh[2][4];
#pragma unroll
            for (int mf = 0; mf < 4; mf++)
                ldsm4(ah[mf], bA + (uint32_t)(aRowBase + mf * 16) * 128 + ga);
#pragma unroll
            for (int ng = 0; ng < 2; ng++)
                ldsm4(bh[ng], bW + (uint32_t)(bRowBase + ng * 16) * 128 + gb);
#pragma unroll
            for (int mf = 0; mf < 4; mf++)
#pragma unroll
                for (int n8 = 0; n8 < 4; n8++)
                    mma16816h(acc[mf][n8], ah[mf], &bh[n8 >> 1][(n8 & 1) * 2]);
        }
        __syncthreads();
    }

    const int mrow0 = by * 128 + (wid & 1) * 64 + (lane >> 2);
    const int ncol0 = bx * 128 + (wid >> 1) * 32 + (lane & 3) * 2;
#pragma unroll
    for (int mf = 0; mf < 4; mf++) {
#pragma unroll
        for (int n8 = 0; n8 < 4; n8++) {
            const int c = ncol0 + n8 * 8;
#pragma unroll
            for (int half_i = 0; half_i < 2; half_i++) {
                const int r = mrow0 + mf * 16 + half_i * 8;
                float v0 = acc[mf][n8][half_i * 2], v1 = acc[mf][n8][half_i * 2 + 1];
                if (EPI == 2 || EPI == 3) { v0 += bias[c]; v1 += bias[c + 1]; }
                if (EPI == 3) {
                    v0 = 0.5f * v0 * (1.0f + erff(v0 * 0.70710678118654752f));
                    v1 = 0.5f * v1 * (1.0f + erff(v1 * 0.70710678118654752f));
                }
                if (EPI == 1) {
                    const size_t i0 = (size_t)(c >> 6) * (ROWS * HD) + (size_t)r * HD + (c & 63);
                    *(__half2*)(Oh + i0) = __halves2half2(__float2half_rn(v0), __float2half_rn(v1));
                } else if (EPI == 3) {
                    const size_t i0 = (size_t)r * N + c;
                    *(__half2*)(Oh + i0) = __halves2half2(__float2half_rn(v0), __float2half_rn(v1));
                } else {
                    *(float2*)(C + (size_t)r * N + c) = make_float2(v0, v1);
                }
            }
        }
    }
}

// ---------------- conversion kernels ----------------
__global__ __launch_bounds__(256)
void tohalf(const float* __restrict__ in, half* __restrict__ hi, int n4)
{
    const int i = blockIdx.x * 256 + threadIdx.x;
    if (i >= n4) return;
    const float4 v = ((const float4*)in)[i];
    ((__half2*)hi)[2 * i]     = __halves2half2(__float2half_rn(v.x), __float2half_rn(v.y));
    ((__half2*)hi)[2 * i + 1] = __halves2half2(__float2half_rn(v.z), __float2half_rn(v.w));
}

template <int PERM>
__global__ __launch_bounds__(256)
void tsplit(const float* __restrict__ W, half* __restrict__ th, int K, int N)
{
    __shared__ float t[32][33];
    const int n0 = blockIdx.x * 32, k0 = blockIdx.y * 32;
    const int tx = threadIdx.x & 31, ty = threadIdx.x >> 5;
#pragma unroll
    for (int j = 0; j < 32; j += 8)
        t[ty + j][tx] = W[(size_t)(k0 + ty + j) * N + n0 + tx];
    __syncthreads();
#pragma unroll
    for (int j = 0; j < 32; j += 8) {
        const float v = t[tx][ty + j];
        const int ocol = n0 + ty + j;
        const int orow = k0 + tx;
        const int srow = (PERM & 1) ? ((ocol & 15) * 64 + (ocol >> 4)) : ocol;
        const int scol = (PERM & 2) ? ((orow & 15) * 64 + (orow >> 4)) : orow;
        th[(size_t)srow * K + scol] = __float2half_rn(v);
    }
}

// ---------------- HMMA fp16 flash attention (values == K) ----------------
// kv super-tile 256 (4 x 64 sub-steps), double-buffered.
// Batch handled via blockIdx.z; batch-split calls use z=1 with pre-offset ptrs.
template <bool MASKED>
__global__ __launch_bounds__(256, 2)
void flash_mma(const half* __restrict__ Qf, const half* __restrict__ Kf,
               const int* __restrict__ mask, half* __restrict__ Oh)
{
    extern __shared__ __align__(1024) char smem[];
    const uint32_t sb = smem_u32(smem);
    const uint32_t sQ = sb;
    const uint32_t sK = sb + 16384;
    float* sMf = (float*)(smem + 81920);
    const int tid = threadIdx.x, wid = tid >> 5, lane = tid & 31;
    const int r7 = lane & 7;
    const int head = blockIdx.y, bat = blockIdx.z;
    const int qr0 = blockIdx.x * 128;
    const size_t hoff = (size_t)head * ROWS * HD;
    const half* gQ = Qf + hoff + (size_t)(bat * SEQ + qr0) * HD;
    const half* gK = Kf + hoff + (size_t)bat * SEQ * HD;

#pragma unroll
    for (int it = 0; it < 4; it++) {
        const int c = tid + it * 256;
        const int r = c >> 3, q = c & 7;
        cp16(sQ + SWZ(r * 128 + q * 16), gQ + (size_t)r * HD + q * 8);
    }
    cp_commit();

    auto load_k = [&](int mt2) {
        const uint32_t kb = sK + (mt2 & 1) * 32768;
#pragma unroll
        for (int it = 0; it < 8; it++) {
            const int c = tid + it * 256;
            const int r = c >> 3, q = c & 7;
            cp16(kb + SWZ(r * 128 + q * 16), gK + (size_t)(mt2 * 256 + r) * HD + q * 8);
        }
        if (MASKED)
            sMf[(mt2 & 1) * 256 + tid] = (float)mask[bat * SEQ + mt2 * 256 + tid];
        cp_commit();
    };
    load_k(0);

    uint32_t aQ[4][4];
    cp_wait<1>();
    __syncthreads();
    {
        const int row = wid * 16 + ((lane >> 3) & 1) * 8 + r7;
        const int g = lane >> 4;
#pragma unroll
        for (int ks = 0; ks < 4; ks++)
            ldsm4(aQ[ks], sQ + (uint32_t)row * 128 + ((((ks << 1) + g) ^ r7) << 4));
    }

    float o[8][4];
#pragma unroll
    for (int j = 0; j < 8; j++) { o[j][0] = o[j][1] = o[j][2] = o[j][3] = 0.f; }
    float lsum0 = 0.f, lsum1 = 0.f;

    const int sRowB = ((lane >> 4) << 3) + r7;
    const int sGran = (lane >> 3) & 1;
    const int tRowB = ((lane >> 3) & 1) * 8 + r7;
    const int tGran = lane >> 4;

    for (int mt2 = 0; mt2 < SEQ / 256; mt2++) {
        const uint32_t kb = sK + (mt2 & 1) * 32768;
        if (mt2 + 1 < SEQ / 256) { load_k(mt2 + 1); cp_wait<1>(); }
        else                     { cp_wait<0>(); }
        __syncthreads();

#pragma unroll
        for (int sub = 0; sub < 4; sub++) {
            const uint32_t ks_base = kb + sub * 8192;
            float s[8][4];
#pragma unroll
            for (int j = 0; j < 8; j++) { s[j][0] = s[j][1] = s[j][2] = s[j][3] = 0.f; }
#pragma unroll
            for (int ks = 0; ks < 4; ks++) {
                const uint32_t gg = ((((ks << 1) + sGran) ^ r7) << 4);
#pragma unroll
                for (int ng = 0; ng < 4; ng++) {
                    uint32_t bh[4];
                    ldsm4(bh, ks_base + (uint32_t)(ng * 16 + sRowB) * 128 + gg);
                    mma16816h(s[2 * ng],     aQ[ks], bh);
                    mma16816h(s[2 * ng + 1], aQ[ks], bh + 2);
                }
            }

            uint32_t ph[8][2];
#pragma unroll
            for (int j = 0; j < 8; j++) {
                if (MASKED) {
                    const int c0 = (mt2 & 1) * 256 + sub * 64 + j * 8 + (lane & 3) * 2;
                    if (sMf[c0]     != 0.f) { s[j][0] = -1e9f; s[j][2] = -1e9f; }
                    if (sMf[c0 + 1] != 0.f) { s[j][1] = -1e9f; s[j][3] = -1e9f; }
                }
                const float p0 = __expf(s[j][0] * 0.125f);
                const float p1 = __expf(s[j][1] * 0.125f);
                const float p2 = __expf(s[j][2] * 0.125f);
                const float p3 = __expf(s[j][3] * 0.125f);
                lsum0 += p0 + p1; lsum1 += p2 + p3;
                ph[j][0] = packh(p0, p1);
                ph[j][1] = packh(p2, p3);
            }

#pragma unroll
            for (int m16 = 0; m16 < 4; m16++) {
                uint32_t ah[4] = {ph[2 * m16][0], ph[2 * m16][1], ph[2 * m16 + 1][0], ph[2 * m16 + 1][1]};
#pragma unroll
                for (int dt = 0; dt < 4; dt++) {
                    uint32_t bh[4];
                    ldsm4t(bh, ks_base + (uint32_t)(m16 * 16 + tRowB) * 128 +
                               ((((dt << 1) + tGran) ^ r7) << 4));
                    mma16816h(o[2 * dt],     ah, bh);
                    mma16816h(o[2 * dt + 1], ah, bh + 2);
                }
            }
        }
        __syncthreads();
    }

    lsum0 += __shfl_xor_sync(0xffffffffu, lsum0, 1);
    lsum0 += __shfl_xor_sync(0xffffffffu, lsum0, 2);
    lsum1 += __shfl_xor_sync(0xffffffffu, lsum1, 1);
    lsum1 += __shfl_xor_sync(0xffffffffu, lsum1, 2);
    const float inv0 = 1.0f / lsum0, inv1 = 1.0f / lsum1;

    const int grow0 = bat * SEQ + qr0 + wid * 16 + (lane >> 2);
#pragma unroll
    for (int j = 0; j < 8; j++) {
        const int d0 = j * 8 + (lane & 3) * 2;
        const size_t b0 = (size_t)grow0 * D_MODEL + head * 64 + d0;
        const size_t b1 = (size_t)(grow0 + 8) * D_MODEL + head * 64 + d0;
        *(__half2*)(Oh + b0) = __halves2half2(
            __float2half_rn(o[j][0] * inv0), __float2half_rn(o[j][1] * inv0));
        *(__half2*)(Oh + b1) = __halves2half2(
            __float2half_rn(o[j][2] * inv1), __float2half_rn(o[j][3] * inv1));
    }
}

// ---------------- fused residual + LayerNorm (+ optional half out) --------
template <bool TOH>
__global__ __launch_bounds__(256)
void add_ln_kernel(const float* __restrict__ X, const float* __restrict__ R,
                   const float* __restrict__ gg, const float* __restrict__ bb,
                   float* __restrict__ O, half* __restrict__ Oh)
{
    const int row = blockIdx.x, t = threadIdx.x;
    const float4 xv = ((const float4*)X)[(size_t)row * 256 + t];
    const float4 rv = ((const float4*)R)[(size_t)row * 256 + t];
    const float v0 = xv.x + rv.x, v1 = xv.y + rv.y, v2 = xv.z + rv.z, v3 = xv.w + rv.w;
    float s  = v0 + v1 + v2 + v3;
    float ss = v0 * v0 + v1 * v1 + v2 * v2 + v3 * v3;
#pragma unroll
    for (int o = 16; o; o >>= 1) {
        s  += __shfl_xor_sync(0xffffffffu, s,  o);
        ss += __shfl_xor_sync(0xffffffffu, ss, o);
    }
    __shared__ float sm[8], sm2[8];
    if ((t & 31) == 0) { sm[t >> 5] = s; sm2[t >> 5] = ss; }
    __syncthreads();
    float ts = 0.f, tss = 0.f;
#pragma unroll
    for (int i = 0; i < 8; i++) { ts += sm[i]; tss += sm2[i]; }
    const float mu   = ts * (1.0f / 1024.0f);
    const float var  = tss * (1.0f / 1024.0f) - mu * mu;
    const float istd = rsqrtf(var + 1e-5f);
    const float4 gv = ((const float4*)gg)[t];
    const float4 bv = ((const float4*)bb)[t];
    float4 ov;
    ov.x = (v0 - mu) * istd * gv.x + bv.x;
    ov.y = (v1 - mu) * istd * gv.y + bv.y;
    ov.z = (v2 - mu) * istd * gv.z + bv.z;
    ov.w = (v3 - mu) * istd * gv.w + bv.w;
    ((float4*)O)[(size_t)row * 256 + t] = ov;
    if (TOH) {
        const size_t base = (size_t)row * 512 + 2 * t;
        ((__half2*)Oh)[base]     = __halves2half2(__float2half_rn(ov.x), __float2half_rn(ov.y));
        ((__half2*)Oh)[base + 1] = __halves2half2(__float2half_rn(ov.z), __float2half_rn(ov.w));
    }
}

// ---------------- launcher ----------------
extern "C" void kernel_launch(void* const* d_in, const int* in_sizes, int n_in,
                              void* d_out, int out_size)
{
    (void)in_sizes; (void)n_in; (void)out_size;
    const float* x    = (const float*)d_in[0];
    const float* enc  = (const float*)d_in[1];
    const int*   mask = (const int*)  d_in[2];
    const float* q1W  = (const float*)d_in[3];
    const float* w1W  = (const float*)d_in[4];
    const float* o1W  = (const float*)d_in[5];
    const float* q2W  = (const float*)d_in[6];
    const float* w2W  = (const float*)d_in[7];
    const float* o2W  = (const float*)d_in[8];
    const float* ffW1 = (const float*)d_in[9];
    const float* ffb1 = (const float*)d_in[10];
    const float* ffW2 = (const float*)d_in[11];
    const float* ffb2 = (const float*)d_in[12];
    const float* g1   = (const float*)d_in[13];
    const float* b1   = (const float*)d_in[14];
    const float* g2   = (const float*)d_in[15];
    const float* b2   = (const float*)d_in[16];
    const float* g3   = (const float*)d_in[17];
    const float* b3   = (const float*)d_in[18];

    float *pq, *pk, *pt0, *pt1, *px1, *px2, *phd;
    half *hid, *wpool;
    cudaGetSymbolAddress((void**)&pq,    g_q);
    cudaGetSymbolAddress((void**)&pk,    g_k);
    cudaGetSymbolAddress((void**)&pt0,   g_t0);
    cudaGetSymbolAddress((void**)&pt1,   g_t1);
    cudaGetSymbolAddress((void**)&px1,   g_x1);
    cudaGetSymbolAddress((void**)&px2,   g_x2);
    cudaGetSymbolAddress((void**)&phd,   g_h);
    cudaGetSymbolAddress((void**)&hid,   g_ah);
    cudaGetSymbolAddress((void**)&wpool, g_w);

    half* actH = (half*)phd;
    half* encH = (half*)pt0;
    half* qh   = (half*)pq;
    half* kh1  = (half*)pk;
    half* kh2  = kh1 + (size_t)NHEADS * ROWS * HD;
    const size_t M1 = 1024 * 1024;
    half* wQ1 = wpool;          half* wK1 = wpool + M1;
    half* wO1 = wpool + 2*M1;   half* wQ2 = wpool + 3*M1;
    half* wK2 = wpool + 4*M1;   half* wO2 = wpool + 5*M1;
    half* wF1 = wpool + 6*M1;   half* wF2 = wpool + 10*M1;

    static cudaStream_t s2 = nullptr, s3 = nullptr;
    static cudaEvent_t evFork, evW1, evO1, evQ2, evO2, evF1, evF2, evK2, evAct, evK1,
                       evLn1, evTailB;
    if (!s2) {
        cudaStreamCreateWithFlags(&s2, cudaStreamNonBlocking);
        cudaStreamCreateWithFlags(&s3, cudaStreamNonBlocking);
        cudaEventCreateWithFlags(&evFork,  cudaEventDisableTiming);
        cudaEventCreateWithFlags(&evW1,    cudaEventDisableTiming);
        cudaEventCreateWithFlags(&evO1,    cudaEventDisableTiming);
        cudaEventCreateWithFlags(&evQ2,    cudaEventDisableTiming);
        cudaEventCreateWithFlags(&evO2,    cudaEventDisableTiming);
        cudaEventCreateWithFlags(&evF1,    cudaEventDisableTiming);
        cudaEventCreateWithFlags(&evF2,    cudaEventDisableTiming);
        cudaEventCreateWithFlags(&evK2,    cudaEventDisableTiming);
        cudaEventCreateWithFlags(&evAct,   cudaEventDisableTiming);
        cudaEventCreateWithFlags(&evK1,    cudaEventDisableTiming);
        cudaEventCreateWithFlags(&evLn1,   cudaEventDisableTiming);
        cudaEventCreateWithFlags(&evTailB, cudaEventDisableTiming);
        cudaFuncSetAttribute(mma_gemm<0>, cudaFuncAttributeMaxDynamicSharedMemorySize, GEMM_SMEM);
        cudaFuncSetAttribute(mma_gemm<1>, cudaFuncAttributeMaxDynamicSharedMemorySize, GEMM_SMEM);
        cudaFuncSetAttribute(mma_gemm<2>, cudaFuncAttributeMaxDynamicSharedMemorySize, GEMM_SMEM);
        cudaFuncSetAttribute(mma_gemm<3>, cudaFuncAttributeMaxDynamicSharedMemorySize, GEMM_SMEM);
        cudaFuncSetAttribute(flash_mma<false>, cudaFuncAttributeMaxDynamicSharedMemorySize, FLASH_SMEM);
        cudaFuncSetAttribute(flash_mma<true>,  cudaFuncAttributeMaxDynamicSharedMemorySize, FLASH_SMEM);
    }

    const dim3 gP(D_MODEL / 128, ROWS / 128);    // (8, 32)
    const dim3 gPh(D_MODEL / 128, ROWS / 256);   // (8, 16)  batch-half
    const dim3 gF1h(MLP / 128, ROWS / 256);      // (32, 16) batch-half
    const dim3 gAttn(SEQ / 128, NHEADS, 2);
    const dim3 gAttnH(SEQ / 128, NHEADS, 1);     // batch-half
    const dim3 tW(D_MODEL / 32, D_MODEL / 32);
    const dim3 tW1(MLP / 32, D_MODEL / 32);
    const dim3 tW2(D_MODEL / 32, MLP / 32);
    const int n4_act = ROWS * D_MODEL / 4;
    const size_t RO_D = (size_t)SEQ * D_MODEL;   // batch-1 offset in model layout
    const size_t RO_H = (size_t)SEQ * HD;        // batch-1 offset in head layout
    const size_t RO_M = (size_t)SEQ * MLP;

    // ---- side stream s2: weight conversions + cross-attn K chain ----
    cudaEventRecord(evFork, 0);
    cudaStreamWaitEvent(s2, evFork, 0);
    tsplit<1><<<tW, 256, 0, s2>>>(w1W, wK1, D_MODEL, D_MODEL);
    cudaEventRecord(evW1, s2);
    tsplit<2><<<tW, 256, 0, s2>>>(o1W, wO1, D_MODEL, D_MODEL);
    cudaEventRecord(evO1, s2);
    tsplit<1><<<tW, 256, 0, s2>>>(q2W, wQ2, D_MODEL, D_MODEL);
    cudaEventRecord(evQ2, s2);
    tsplit<2><<<tW, 256, 0, s2>>>(o2W, wO2, D_MODEL, D_MODEL);
    cudaEventRecord(evO2, s2);
    tsplit<0><<<tW1, 256, 0, s2>>>(ffW1, wF1, D_MODEL, MLP);
    cudaEventRecord(evF1, s2);
    tsplit<0><<<tW2, 256, 0, s2>>>(ffW2, wF2, MLP, D_MODEL);
    cudaEventRecord(evF2, s2);
    tohalf<<<(n4_act + 255) / 256, 256, 0, s2>>>(enc, encH, n4_act);
    tsplit<1><<<tW, 256, 0, s2>>>(w2W, wK2, D_MODEL, D_MODEL);
    mma_gemm<1><<<gP, 256, GEMM_SMEM, s2>>>(encH, wK2, nullptr, nullptr, kh2, D_MODEL, D_MODEL);
    cudaEventRecord(evK2, s2);

    // ---- main chain: self-attention; K1 proj concurrent on s3 ----
    tohalf<<<(n4_act + 255) / 256, 256>>>(x, actH, n4_act);
    tsplit<1><<<tW, 256>>>(q1W, wQ1, D_MODEL, D_MODEL);
    cudaEventRecord(evAct, 0);
    cudaStreamWaitEvent(s3, evAct, 0);
    cudaStreamWaitEvent(s3, evW1, 0);
    mma_gemm<1><<<gP, 256, GEMM_SMEM, s3>>>(actH, wK1, nullptr, nullptr, kh1, D_MODEL, D_MODEL);
    cudaEventRecord(evK1, s3);
    mma_gemm<1><<<gP, 256, GEMM_SMEM>>>(actH, wQ1, nullptr, nullptr, qh, D_MODEL, D_MODEL);
    cudaStreamWaitEvent(0, evK1, 0);
    flash_mma<false><<<gAttn, 256, FLASH_SMEM>>>(qh, kh1, nullptr, actH);
    cudaStreamWaitEvent(0, evO1, 0);
    mma_gemm<0><<<gP, 256, GEMM_SMEM>>>(actH, wO1, nullptr, pt1, nullptr, D_MODEL, D_MODEL);
    add_ln_kernel<true><<<ROWS, 256>>>(x, pt1, g1, b1, px1, actH);
    cudaEventRecord(evLn1, 0);

    // ---- post-LN1 tail: batch-split pipeline (main = batch 0, s3 = batch 1) ----
    // s3 (batch 1)
    cudaStreamWaitEvent(s3, evLn1, 0);
    cudaStreamWaitEvent(s3, evQ2, 0);
    mma_gemm<1><<<gPh, 256, GEMM_SMEM, s3>>>(actH + RO_D, wQ2, nullptr, nullptr,
                                             qh + RO_H, D_MODEL, D_MODEL);
    cudaStreamWaitEvent(s3, evK2, 0);
    flash_mma<true><<<gAttnH, 256, FLASH_SMEM, s3>>>(qh + RO_H, kh2 + RO_H,
                                                     mask + SEQ, actH + RO_D);
    cudaStreamWaitEvent(s3, evO2, 0);
    mma_gemm<0><<<gPh, 256, GEMM_SMEM, s3>>>(actH + RO_D, wO2, nullptr,
                                             pt1 + RO_D, nullptr, D_MODEL, D_MODEL);
    add_ln_kernel<true><<<SEQ, 256, 0, s3>>>(px1 + RO_D, pt1 + RO_D, g2, b2,
                                             px2 + RO_D, actH + RO_D);
    cudaStreamWaitEvent(s3, evF1, 0);
    mma_gemm<3><<<gF1h, 256, GEMM_SMEM, s3>>>(actH + RO_D, wF1, ffb1, nullptr,
                                              hid + RO_M, MLP, D_MODEL);
    cudaStreamWaitEvent(s3, evF2, 0);
    mma_gemm<2><<<gPh, 256, GEMM_SMEM, s3>>>(hid + RO_M, wF2, ffb2,
                                             pt1 + RO_D, nullptr, D_MODEL, MLP);
    add_ln_kernel<false><<<SEQ, 256, 0, s3>>>(px2 + RO_D, pt1 + RO_D, g3, b3,
                                              (float*)d_out + RO_D, nullptr);
    cudaEventRecord(evTailB, s3);

    // main (batch 0)
    cudaStreamWaitEvent(0, evQ2, 0);
    mma_gemm<1><<<gPh, 256, GEMM_SMEM>>>(actH, wQ2, nullptr, nullptr, qh, D_MODEL, D_MODEL);
    cudaStreamWaitEvent(0, evK2, 0);
    flash_mma<true><<<gAttnH, 256, FLASH_SMEM>>>(qh, kh2, mask, actH);
    cudaStreamWaitEvent(0, evO2, 0);
    mma_gemm<0><<<gPh, 256, GEMM_SMEM>>>(actH, wO2, nullptr, pt1, nullptr, D_MODEL, D_MODEL);
    add_ln_kernel<true><<<SEQ, 256>>>(px1, pt1, g2, b2, px2, actH);
    cudaStreamWaitEvent(0, evF1, 0);
    mma_gemm<3><<<gF1h, 256, GEMM_SMEM>>>(actH, wF1, ffb1, nullptr, hid, MLP, D_MODEL);
    cudaStreamWaitEvent(0, evF2, 0);
    mma_gemm<2><<<gPh, 256, GEMM_SMEM>>>(hid, wF2, ffb2, pt1, nullptr, D_MODEL, MLP);
    add_ln_kernel<false><<<SEQ, 256>>>(px2, pt1, g3, b3, (float*)d_out, nullptr);
    cudaStreamWaitEvent(0, evTailB, 0);
}

// round 17
// speedup vs baseline: 1.6203x; 1.0119x over previous
#include <cuda_runtime.h>
#include <cuda_fp16.h>
#include <math.h>
#include <stdint.h>

#define D_MODEL 1024
#define NHEADS  16
#define HD      64
#define SEQ     2048
#define ROWS    4096   // B * SEQ
#define MLP     4096

// ---------------- scratch (static device memory; no allocs) ----------------
__device__ float g_q [NHEADS * ROWS * HD];     // 16 MB -> qh half pool
__device__ float g_k [NHEADS * ROWS * HD];     // 16 MB -> kh1 + kh2 half pools
__device__ float g_t0[ROWS * D_MODEL];         // enc half
__device__ float g_t1[ROWS * D_MODEL];         // fp32 gemm outputs
__device__ float g_x1[ROWS * D_MODEL];
__device__ float g_x2[ROWS * D_MODEL];
__device__ float g_h [ROWS * MLP];             // act half
__device__ half  g_ah[ROWS * MLP];             // 32 MB hid (GELU out)
__device__ half  g_w [14 * 1024 * 1024];       // 28 MB weight pool

// ---------------- PTX helpers ----------------
__device__ __forceinline__ uint32_t smem_u32(const void* p) {
    uint32_t a;
    asm("{ .reg .u64 t; cvta.to.shared.u64 t, %1; cvt.u32.u64 %0, t; }" : "=r"(a) : "l"(p));
    return a;
}
__device__ __forceinline__ void cp16(uint32_t dst, const void* src) {
    asm volatile("cp.async.cg.shared.global [%0], [%1], 16;" :: "r"(dst), "l"(src));
}
__device__ __forceinline__ void cp_commit() { asm volatile("cp.async.commit_group;"); }
template <int N> __device__ __forceinline__ void cp_wait() {
    asm volatile("cp.async.wait_group %0;" :: "n"(N) : "memory");
}
__device__ __forceinline__ void ldsm4(uint32_t* r, uint32_t a) {
    asm volatile("ldmatrix.sync.aligned.m8n8.x4.shared.b16 {%0,%1,%2,%3}, [%4];"
                 : "=r"(r[0]), "=r"(r[1]), "=r"(r[2]), "=r"(r[3]) : "r"(a));
}
__device__ __forceinline__ void ldsm4t(uint32_t* r, uint32_t a) {
    asm volatile("ldmatrix.sync.aligned.m8n8.x4.trans.shared.b16 {%0,%1,%2,%3}, [%4];"
                 : "=r"(r[0]), "=r"(r[1]), "=r"(r[2]), "=r"(r[3]) : "r"(a));
}
__device__ __forceinline__ void mma16816h(float* d, const uint32_t* a, const uint32_t* b) {
    asm volatile("mma.sync.aligned.m16n8k16.row.col.f32.f16.f16.f32 "
                 "{%0,%1,%2,%3}, {%4,%5,%6,%7}, {%8,%9}, {%0,%1,%2,%3};"
                 : "+f"(d[0]), "+f"(d[1]), "+f"(d[2]), "+f"(d[3])
                 : "r"(a[0]), "r"(a[1]), "r"(a[2]), "r"(a[3]), "r"(b[0]), "r"(b[1]));
}
__device__ __forceinline__ uint32_t packh(float a, float b) {
    __half2 t = __halves2half2(__float2half_rn(a), __float2half_rn(b));
    return *(uint32_t*)&t;
}

#define SWZ(x) ((x) ^ ((((uint32_t)(x)) >> 3) & 0x70))
#define SOFF(b) ((b) * 32768u)
#define GEMM_SMEM 98304
#define FLASH_SMEM 84992   // Q 16K + K 2x32K + mask 2K + pad

// ---------------- HMMA fp16 GEMM (128x128, 3-stage, 256 thr, occ 2) -------
// EPI: 0 fp32 C; 1 single-half head-contig; 2 +bias fp32; 3 +bias+GELU half.
template <int EPI>
__global__ __launch_bounds__(256, 2)
void mma_gemm(const half* __restrict__ A, const half* __restrict__ W,
              const float* __restrict__ bias, float* __restrict__ C,
              half* __restrict__ Oh, int N, int K)
{
    extern __shared__ __align__(1024) char smem[];
    const uint32_t sb = smem_u32(smem);
    const int tid = threadIdx.x, wid = tid >> 5, lane = tid & 31;
    const int bx = blockIdx.x, by = blockIdx.y;
    const int rowA0 = by * 128, rowB0 = bx * 128;

    const int r7 = lane & 7;
    const int aRowBase = (wid & 1) * 64 + ((lane >> 3) & 1) * 8 + r7;
    const int aGranLane = lane >> 4;
    const int bRowBase = (wid >> 1) * 32 + ((lane >> 4) << 3) + r7;
    const int bGranLane = (lane >> 3) & 1;

    float acc[4][4][4];
#pragma unroll
    for (int i = 0; i < 4; i++)
#pragma unroll
        for (int j = 0; j < 4; j++)
#pragma unroll
            for (int v = 0; v < 4; v++) acc[i][j][v] = 0.f;

    const int NCH = K >> 6;

    auto load_chunk = [&](int i, int b) {
        const int k0 = i << 6;
        const uint32_t st = sb + SOFF(b);
#pragma unroll
        for (int it = 0; it < 4; it++) {
            const int c = tid + it * 256;
            const int r = c >> 3, q = c & 7;
            const uint32_t d = SWZ(r * 128 + q * 16);
            cp16(st + d,         A + (size_t)(rowA0 + r) * K + k0 + q * 8);
            cp16(st + 16384 + d, W + (size_t)(rowB0 + r) * K + k0 + q * 8);
        }
        cp_commit();
    };

    load_chunk(0, 0);
    load_chunk(1, 1);

    for (int i = 0; i < NCH; i++) {
        const int b = i % 3;
        if (i + 2 < NCH)      { load_chunk(i + 2, (i + 2) % 3); cp_wait<2>(); }
        else if (i + 1 < NCH) { cp_wait<1>(); }
        else                  { cp_wait<0>(); }
        __syncthreads();

        const uint32_t bA = sb + SOFF(b), bW = bA + 16384;
#pragma unroll
        for (int ks = 0; ks < 4; ks++) {
            const int ga = ((2 * ks + aGranLane) ^ r7) << 4;
            const int gb = ((2 * ks + bGranLane) ^ r7) << 4;
            uint32_t ah[4][4], bh[2][4];
#pragma unroll
            for (int mf = 0; mf < 4; mf++)
                ldsm4(ah[mf], bA + (uint32_t)(aRowBase + mf * 16) * 128 + ga);
#pragma unroll
            for (int ng = 0; ng < 2; ng++)
                ldsm4(bh[ng], bW + (uint32_t)(bRowBase + ng * 16) * 128 + gb);
#pragma unroll
            for (int mf = 0; mf < 4; mf++)
#pragma unroll
                for (int n8 = 0; n8 < 4; n8++)
                    mma16816h(acc[mf][n8], ah[mf], &bh[n8 >> 1][(n8 & 1) * 2]);
        }
        __syncthreads();
    }

    const int mrow0 = by * 128 + (wid & 1) * 64 + (lane >> 2);
    const int ncol0 = bx * 128 + (wid >> 1) * 32 + (lane & 3) * 2;
#pragma unroll
    for (int mf = 0; mf < 4; mf++) {
#pragma unroll
        for (int n8 = 0; n8 < 4; n8++) {
            const int c = ncol0 + n8 * 8;
#pragma unroll
            for (int half_i = 0; half_i < 2; half_i++) {
                const int r = mrow0 + mf * 16 + half_i * 8;
                float v0 = acc[mf][n8][half_i * 2], v1 = acc[mf][n8][half_i * 2 + 1];
                if (EPI == 2 || EPI == 3) { v0 += bias[c]; v1 += bias[c + 1]; }
                if (EPI == 3) {
                    v0 = 0.5f * v0 * (1.0f + erff(v0 * 0.70710678118654752f));
                    v1 = 0.5f * v1 * (1.0f + erff(v1 * 0.70710678118654752f));
                }
                if (EPI == 1) {
                    const size_t i0 = (size_t)(c >> 6) * (ROWS * HD) + (size_t)r * HD + (c & 63);
                    *(__half2*)(Oh + i0) = __halves2half2(__float2half_rn(v0), __float2half_rn(v1));
                } else if (EPI == 3) {
                    const size_t i0 = (size_t)r * N + c;
                    *(__half2*)(Oh + i0) = __halves2half2(__float2half_rn(v0), __float2half_rn(v1));
                } else {
                    *(float2*)(C + (size_t)r * N + c) = make_float2(v0, v1);
                }
            }
        }
    }
}

// ---------------- conversion kernels ----------------
__global__ __launch_bounds__(256)
void tohalf(const float* __restrict__ in, half* __restrict__ hi, int n4)
{
    const int i = blockIdx.x * 256 + threadIdx.x;
    if (i >= n4) return;
    const float4 v = ((const float4*)in)[i];
    ((__half2*)hi)[2 * i]     = __halves2half2(__float2half_rn(v.x), __float2half_rn(v.y));
    ((__half2*)hi)[2 * i + 1] = __halves2half2(__float2half_rn(v.z), __float2half_rn(v.w));
}

template <int PERM>
__global__ __launch_bounds__(256)
void tsplit(const float* __restrict__ W, half* __restrict__ th, int K, int N)
{
    __shared__ float t[32][33];
    const int n0 = blockIdx.x * 32, k0 = blockIdx.y * 32;
    const int tx = threadIdx.x & 31, ty = threadIdx.x >> 5;
#pragma unroll
    for (int j = 0; j < 32; j += 8)
        t[ty + j][tx] = W[(size_t)(k0 + ty + j) * N + n0 + tx];
    __syncthreads();
#pragma unroll
    for (int j = 0; j < 32; j += 8) {
        const float v = t[tx][ty + j];
        const int ocol = n0 + ty + j;
        const int orow = k0 + tx;
        const int srow = (PERM & 1) ? ((ocol & 15) * 64 + (ocol >> 4)) : ocol;
        const int scol = (PERM & 2) ? ((orow & 15) * 64 + (orow >> 4)) : orow;
        th[(size_t)srow * K + scol] = __float2half_rn(v);
    }
}

// ---------------- HMMA fp16 flash attention (values == K) ----------------
// kv super-tile 256 (4 x 64 sub-steps), double-buffered.
// Batch-lane calls use gridDim.z = 1 with pre-offset pointers (bat = 0).
template <bool MASKED>
__global__ __launch_bounds__(256, 2)
void flash_mma(const half* __restrict__ Qf, const half* __restrict__ Kf,
               const int* __restrict__ mask, half* __restrict__ Oh)
{
    extern __shared__ __align__(1024) char smem[];
    const uint32_t sb = smem_u32(smem);
    const uint32_t sQ = sb;
    const uint32_t sK = sb + 16384;
    float* sMf = (float*)(smem + 81920);
    const int tid = threadIdx.x, wid = tid >> 5, lane = tid & 31;
    const int r7 = lane & 7;
    const int head = blockIdx.y, bat = blockIdx.z;
    const int qr0 = blockIdx.x * 128;
    const size_t hoff = (size_t)head * ROWS * HD;
    const half* gQ = Qf + hoff + (size_t)(bat * SEQ + qr0) * HD;
    const half* gK = Kf + hoff + (size_t)bat * SEQ * HD;

#pragma unroll
    for (int it = 0; it < 4; it++) {
        const int c = tid + it * 256;
        const int r = c >> 3, q = c & 7;
        cp16(sQ + SWZ(r * 128 + q * 16), gQ + (size_t)r * HD + q * 8);
    }
    cp_commit();

    auto load_k = [&](int mt2) {
        const uint32_t kb = sK + (mt2 & 1) * 32768;
#pragma unroll
        for (int it = 0; it < 8; it++) {
            const int c = tid + it * 256;
            const int r = c >> 3, q = c & 7;
            cp16(kb + SWZ(r * 128 + q * 16), gK + (size_t)(mt2 * 256 + r) * HD + q * 8);
        }
        if (MASKED)
            sMf[(mt2 & 1) * 256 + tid] = (float)mask[bat * SEQ + mt2 * 256 + tid];
        cp_commit();
    };
    load_k(0);

    uint32_t aQ[4][4];
    cp_wait<1>();
    __syncthreads();
    {
        const int row = wid * 16 + ((lane >> 3) & 1) * 8 + r7;
        const int g = lane >> 4;
#pragma unroll
        for (int ks = 0; ks < 4; ks++)
            ldsm4(aQ[ks], sQ + (uint32_t)row * 128 + ((((ks << 1) + g) ^ r7) << 4));
    }

    float o[8][4];
#pragma unroll
    for (int j = 0; j < 8; j++) { o[j][0] = o[j][1] = o[j][2] = o[j][3] = 0.f; }
    float lsum0 = 0.f, lsum1 = 0.f;

    const int sRowB = ((lane >> 4) << 3) + r7;
    const int sGran = (lane >> 3) & 1;
    const int tRowB = ((lane >> 3) & 1) * 8 + r7;
    const int tGran = lane >> 4;

    for (int mt2 = 0; mt2 < SEQ / 256; mt2++) {
        const uint32_t kb = sK + (mt2 & 1) * 32768;
        if (mt2 + 1 < SEQ / 256) { load_k(mt2 + 1); cp_wait<1>(); }
        else                     { cp_wait<0>(); }
        __syncthreads();

#pragma unroll
        for (int sub = 0; sub < 4; sub++) {
            const uint32_t ks_base = kb + sub * 8192;
            float s[8][4];
#pragma unroll
            for (int j = 0; j < 8; j++) { s[j][0] = s[j][1] = s[j][2] = s[j][3] = 0.f; }
#pragma unroll
            for (int ks = 0; ks < 4; ks++) {
                const uint32_t gg = ((((ks << 1) + sGran) ^ r7) << 4);
#pragma unroll
                for (int ng = 0; ng < 4; ng++) {
                    uint32_t bh[4];
                    ldsm4(bh, ks_base + (uint32_t)(ng * 16 + sRowB) * 128 + gg);
                    mma16816h(s[2 * ng],     aQ[ks], bh);
                    mma16816h(s[2 * ng + 1], aQ[ks], bh + 2);
                }
            }

            uint32_t ph[8][2];
#pragma unroll
            for (int j = 0; j < 8; j++) {
                if (MASKED) {
                    const int c0 = (mt2 & 1) * 256 + sub * 64 + j * 8 + (lane & 3) * 2;
                    if (sMf[c0]     != 0.f) { s[j][0] = -1e9f; s[j][2] = -1e9f; }
                    if (sMf[c0 + 1] != 0.f) { s[j][1] = -1e9f; s[j][3] = -1e9f; }
                }
                const float p0 = __expf(s[j][0] * 0.125f);
                const float p1 = __expf(s[j][1] * 0.125f);
                const float p2 = __expf(s[j][2] * 0.125f);
                const float p3 = __expf(s[j][3] * 0.125f);
                lsum0 += p0 + p1; lsum1 += p2 + p3;
                ph[j][0] = packh(p0, p1);
                ph[j][1] = packh(p2, p3);
            }

#pragma unroll
            for (int m16 = 0; m16 < 4; m16++) {
                uint32_t ah[4] = {ph[2 * m16][0], ph[2 * m16][1], ph[2 * m16 + 1][0], ph[2 * m16 + 1][1]};
#pragma unroll
                for (int dt = 0; dt < 4; dt++) {
                    uint32_t bh[4];
                    ldsm4t(bh, ks_base + (uint32_t)(m16 * 16 + tRowB) * 128 +
                               ((((dt << 1) + tGran) ^ r7) << 4));
                    mma16816h(o[2 * dt],     ah, bh);
                    mma16816h(o[2 * dt + 1], ah, bh + 2);
                }
            }
        }
        __syncthreads();
    }

    lsum0 += __shfl_xor_sync(0xffffffffu, lsum0, 1);
    lsum0 += __shfl_xor_sync(0xffffffffu, lsum0, 2);
    lsum1 += __shfl_xor_sync(0xffffffffu, lsum1, 1);
    lsum1 += __shfl_xor_sync(0xffffffffu, lsum1, 2);
    const float inv0 = 1.0f / lsum0, inv1 = 1.0f / lsum1;

    const int grow0 = bat * SEQ + qr0 + wid * 16 + (lane >> 2);
#pragma unroll
    for (int j = 0; j < 8; j++) {
        const int d0 = j * 8 + (lane & 3) * 2;
        const size_t b0 = (size_t)grow0 * D_MODEL + head * 64 + d0;
        const size_t b1 = (size_t)(grow0 + 8) * D_MODEL + head * 64 + d0;
        *(__half2*)(Oh + b0) = __halves2half2(
            __float2half_rn(o[j][0] * inv0), __float2half_rn(o[j][1] * inv0));
        *(__half2*)(Oh + b1) = __halves2half2(
            __float2half_rn(o[j][2] * inv1), __float2half_rn(o[j][3] * inv1));
    }
}

// ---------------- fused residual + LayerNorm (+ optional half out) --------
template <bool TOH>
__global__ __launch_bounds__(256)
void add_ln_kernel(const float* __restrict__ X, const float* __restrict__ R,
                   const float* __restrict__ gg, const float* __restrict__ bb,
                   float* __restrict__ O, half* __restrict__ Oh)
{
    const int row = blockIdx.x, t = threadIdx.x;
    const float4 xv = ((const float4*)X)[(size_t)row * 256 + t];
    const float4 rv = ((const float4*)R)[(size_t)row * 256 + t];
    const float v0 = xv.x + rv.x, v1 = xv.y + rv.y, v2 = xv.z + rv.z, v3 = xv.w + rv.w;
    float s  = v0 + v1 + v2 + v3;
    float ss = v0 * v0 + v1 * v1 + v2 * v2 + v3 * v3;
#pragma unroll
    for (int o = 16; o; o >>= 1) {
        s  += __shfl_xor_sync(0xffffffffu, s,  o);
        ss += __shfl_xor_sync(0xffffffffu, ss, o);
    }
    __shared__ float sm[8], sm2[8];
    if ((t & 31) == 0) { sm[t >> 5] = s; sm2[t >> 5] = ss; }
    __syncthreads();
    float ts = 0.f, tss = 0.f;
#pragma unroll
    for (int i = 0; i < 8; i++) { ts += sm[i]; tss += sm2[i]; }
    const float mu   = ts * (1.0f / 1024.0f);
    const float var  = tss * (1.0f / 1024.0f) - mu * mu;
    const float istd = rsqrtf(var + 1e-5f);
    const float4 gv = ((const float4*)gg)[t];
    const float4 bv = ((const float4*)bb)[t];
    float4 ov;
    ov.x = (v0 - mu) * istd * gv.x + bv.x;
    ov.y = (v1 - mu) * istd * gv.y + bv.y;
    ov.z = (v2 - mu) * istd * gv.z + bv.z;
    ov.w = (v3 - mu) * istd * gv.w + bv.w;
    ((float4*)O)[(size_t)row * 256 + t] = ov;
    if (TOH) {
        const size_t base = (size_t)row * 512 + 2 * t;
        ((__half2*)Oh)[base]     = __halves2half2(__float2half_rn(ov.x), __float2half_rn(ov.y));
        ((__half2*)Oh)[base + 1] = __halves2half2(__float2half_rn(ov.z), __float2half_rn(ov.w));
    }
}

// ---------------- launcher ----------------
extern "C" void kernel_launch(void* const* d_in, const int* in_sizes, int n_in,
                              void* d_out, int out_size)
{
    (void)in_sizes; (void)n_in; (void)out_size;
    const float* x    = (const float*)d_in[0];
    const float* enc  = (const float*)d_in[1];
    const int*   mask = (const int*)  d_in[2];
    const float* q1W  = (const float*)d_in[3];
    const float* w1W  = (const float*)d_in[4];
    const float* o1W  = (const float*)d_in[5];
    const float* q2W  = (const float*)d_in[6];
    const float* w2W  = (const float*)d_in[7];
    const float* o2W  = (const float*)d_in[8];
    const float* ffW1 = (const float*)d_in[9];
    const float* ffb1 = (const float*)d_in[10];
    const float* ffW2 = (const float*)d_in[11];
    const float* ffb2 = (const float*)d_in[12];
    const float* g1   = (const float*)d_in[13];
    const float* b1   = (const float*)d_in[14];
    const float* g2   = (const float*)d_in[15];
    const float* b2   = (const float*)d_in[16];
    const float* g3   = (const float*)d_in[17];
    const float* b3   = (const float*)d_in[18];

    float *pq, *pk, *pt0, *pt1, *px1, *px2, *phd;
    half *hid, *wpool;
    cudaGetSymbolAddress((void**)&pq,    g_q);
    cudaGetSymbolAddress((void**)&pk,    g_k);
    cudaGetSymbolAddress((void**)&pt0,   g_t0);
    cudaGetSymbolAddress((void**)&pt1,   g_t1);
    cudaGetSymbolAddress((void**)&px1,   g_x1);
    cudaGetSymbolAddress((void**)&px2,   g_x2);
    cudaGetSymbolAddress((void**)&phd,   g_h);
    cudaGetSymbolAddress((void**)&hid,   g_ah);
    cudaGetSymbolAddress((void**)&wpool, g_w);

    half* actH = (half*)phd;
    half* encH = (half*)pt0;
    half* qh   = (half*)pq;
    half* kh1  = (half*)pk;
    half* kh2  = kh1 + (size_t)NHEADS * ROWS * HD;
    const size_t M1 = 1024 * 1024;
    half* wQ1 = wpool;          half* wK1 = wpool + M1;
    half* wO1 = wpool + 2*M1;   half* wQ2 = wpool + 3*M1;
    half* wK2 = wpool + 4*M1;   half* wO2 = wpool + 5*M1;
    half* wF1 = wpool + 6*M1;   half* wF2 = wpool + 10*M1;

    static cudaStream_t s2 = nullptr, s3 = nullptr;
    static cudaEvent_t evFork, evW1, evO1, evQ2, evO2, evF1, evF2, evK2, evAct, evQ1W,
                       evTailB;
    if (!s2) {
        cudaStreamCreateWithFlags(&s2, cudaStreamNonBlocking);
        cudaStreamCreateWithFlags(&s3, cudaStreamNonBlocking);
        cudaEventCreateWithFlags(&evFork,  cudaEventDisableTiming);
        cudaEventCreateWithFlags(&evW1,    cudaEventDisableTiming);
        cudaEventCreateWithFlags(&evO1,    cudaEventDisableTiming);
        cudaEventCreateWithFlags(&evQ2,    cudaEventDisableTiming);
        cudaEventCreateWithFlags(&evO2,    cudaEventDisableTiming);
        cudaEventCreateWithFlags(&evF1,    cudaEventDisableTiming);
        cudaEventCreateWithFlags(&evF2,    cudaEventDisableTiming);
        cudaEventCreateWithFlags(&evK2,    cudaEventDisableTiming);
        cudaEventCreateWithFlags(&evAct,   cudaEventDisableTiming);
        cudaEventCreateWithFlags(&evQ1W,   cudaEventDisableTiming);
        cudaEventCreateWithFlags(&evTailB, cudaEventDisableTiming);
        cudaFuncSetAttribute(mma_gemm<0>, cudaFuncAttributeMaxDynamicSharedMemorySize, GEMM_SMEM);
        cudaFuncSetAttribute(mma_gemm<1>, cudaFuncAttributeMaxDynamicSharedMemorySize, GEMM_SMEM);
        cudaFuncSetAttribute(mma_gemm<2>, cudaFuncAttributeMaxDynamicSharedMemorySize, GEMM_SMEM);
        cudaFuncSetAttribute(mma_gemm<3>, cudaFuncAttributeMaxDynamicSharedMemorySize, GEMM_SMEM);
        cudaFuncSetAttribute(flash_mma<false>, cudaFuncAttributeMaxDynamicSharedMemorySize, FLASH_SMEM);
        cudaFuncSetAttribute(flash_mma<true>,  cudaFuncAttributeMaxDynamicSharedMemorySize, FLASH_SMEM);
    }

    const dim3 gP(D_MODEL / 128, ROWS / 128);    // (8, 32)  full (kh2 on s2)
    const dim3 gPh(D_MODEL / 128, ROWS / 256);   // (8, 16)  batch-half
    const dim3 gF1h(MLP / 128, ROWS / 256);      // (32, 16) batch-half
    const dim3 gAttnH(SEQ / 128, NHEADS, 1);     // batch-half
    const dim3 tW(D_MODEL / 32, D_MODEL / 32);
    const dim3 tW1(MLP / 32, D_MODEL / 32);
    const dim3 tW2(D_MODEL / 32, MLP / 32);
    const int n4_act = ROWS * D_MODEL / 4;
    const size_t RO_D = (size_t)SEQ * D_MODEL;   // batch-1 offset (model layout)
    const size_t RO_H = (size_t)SEQ * HD;        // batch-1 offset (head layout)
    const size_t RO_M = (size_t)SEQ * MLP;

    // ---- side stream s2: weight conversions (deadline order) + kh2 full ----
    cudaEventRecord(evFork, 0);
    cudaStreamWaitEvent(s2, evFork, 0);
    tsplit<1><<<tW, 256, 0, s2>>>(w1W, wK1, D_MODEL, D_MODEL);
    cudaEventRecord(evW1, s2);
    tsplit<2><<<tW, 256, 0, s2>>>(o1W, wO1, D_MODEL, D_MODEL);
    cudaEventRecord(evO1, s2);
    tsplit<1><<<tW, 256, 0, s2>>>(q2W, wQ2, D_MODEL, D_MODEL);
    cudaEventRecord(evQ2, s2);
    tsplit<2><<<tW, 256, 0, s2>>>(o2W, wO2, D_MODEL, D_MODEL);
    cudaEventRecord(evO2, s2);
    tsplit<0><<<tW1, 256, 0, s2>>>(ffW1, wF1, D_MODEL, MLP);
    cudaEventRecord(evF1, s2);
    tsplit<0><<<tW2, 256, 0, s2>>>(ffW2, wF2, MLP, D_MODEL);
    cudaEventRecord(evF2, s2);
    tohalf<<<(n4_act + 255) / 256, 256, 0, s2>>>(enc, encH, n4_act);
    tsplit<1><<<tW, 256, 0, s2>>>(w2W, wK2, D_MODEL, D_MODEL);
    mma_gemm<1><<<gP, 256, GEMM_SMEM, s2>>>(encH, wK2, nullptr, nullptr, kh2, D_MODEL, D_MODEL);
    cudaEventRecord(evK2, s2);

    // ---- shared prologue on main: activations + q1 weight ----
    tohalf<<<(n4_act + 255) / 256, 256>>>(x, actH, n4_act);
    cudaEventRecord(evAct, 0);
    tsplit<1><<<tW, 256>>>(q1W, wQ1, D_MODEL, D_MODEL);
    cudaEventRecord(evQ1W, 0);

    // ================= lane s3: batch 1 end-to-end =================
    cudaStreamWaitEvent(s3, evAct, 0);
    cudaStreamWaitEvent(s3, evQ1W, 0);
    mma_gemm<1><<<gPh, 256, GEMM_SMEM, s3>>>(actH + RO_D, wQ1, nullptr, nullptr,
                                             qh + RO_H, D_MODEL, D_MODEL);
    cudaStreamWaitEvent(s3, evW1, 0);
    mma_gemm<1><<<gPh, 256, GEMM_SMEM, s3>>>(actH + RO_D, wK1, nullptr, nullptr,
                                             kh1 + RO_H, D_MODEL, D_MODEL);
    flash_mma<false><<<gAttnH, 256, FLASH_SMEM, s3>>>(qh + RO_H, kh1 + RO_H,
                                                      nullptr, actH + RO_D);
    cudaStreamWaitEvent(s3, evO1, 0);
    mma_gemm<0><<<gPh, 256, GEMM_SMEM, s3>>>(actH + RO_D, wO1, nullptr,
                                             pt1 + RO_D, nullptr, D_MODEL, D_MODEL);
    add_ln_kernel<true><<<SEQ, 256, 0, s3>>>(x + RO_D, pt1 + RO_D, g1, b1,
                                             px1 + RO_D, actH + RO_D);
    cudaStreamWaitEvent(s3, evQ2, 0);
    mma_gemm<1><<<gPh, 256, GEMM_SMEM, s3>>>(actH + RO_D, wQ2, nullptr, nullptr,
                                             qh + RO_H, D_MODEL, D_MODEL);
    cudaStreamWaitEvent(s3, evK2, 0);
    flash_mma<true><<<gAttnH, 256, FLASH_SMEM, s3>>>(qh + RO_H, kh2 + RO_H,
                                                     mask + SEQ, actH + RO_D);
    cudaStreamWaitEvent(s3, evO2, 0);
    mma_gemm<0><<<gPh, 256, GEMM_SMEM, s3>>>(actH + RO_D, wO2, nullptr,
                                             pt1 + RO_D, nullptr, D_MODEL, D_MODEL);
    add_ln_kernel<true><<<SEQ, 256, 0, s3>>>(px1 + RO_D, pt1 + RO_D, g2, b2,
                                             px2 + RO_D, actH + RO_D);
    cudaStreamWaitEvent(s3, evF1, 0);
    mma_gemm<3><<<gF1h, 256, GEMM_SMEM, s3>>>(actH + RO_D, wF1, ffb1, nullptr,
                                              hid + RO_M, MLP, D_MODEL);
    cudaStreamWaitEvent(s3, evF2, 0);
    mma_gemm<2><<<gPh, 256, GEMM_SMEM, s3>>>(hid + RO_M, wF2, ffb2,
                                             pt1 + RO_D, nullptr, D_MODEL, MLP);
    add_ln_kernel<false><<<SEQ, 256, 0, s3>>>(px2 + RO_D, pt1 + RO_D, g3, b3,
                                              (float*)d_out + RO_D, nullptr);
    cudaEventRecord(evTailB, s3);

    // ================= lane main: batch 0 end-to-end =================
    mma_gemm<1><<<gPh, 256, GEMM_SMEM>>>(actH, wQ1, nullptr, nullptr, qh, D_MODEL, D_MODEL);
    cudaStreamWaitEvent(0, evW1, 0);
    mma_gemm<1><<<gPh, 256, GEMM_SMEM>>>(actH, wK1, nullptr, nullptr, kh1, D_MODEL, D_MODEL);
    flash_mma<false><<<gAttnH, 256, FLASH_SMEM>>>(qh, kh1, nullptr, actH);
    cudaStreamWaitEvent(0, evO1, 0);
    mma_gemm<0><<<gPh, 256, GEMM_SMEM>>>(actH, wO1, nullptr, pt1, nullptr, D_MODEL, D_MODEL);
    add_ln_kernel<true><<<SEQ, 256>>>(x, pt1, g1, b1, px1, actH);
    cudaStreamWaitEvent(0, evQ2, 0);
    mma_gemm<1><<<gPh, 256, GEMM_SMEM>>>(actH, wQ2, nullptr, nullptr, qh, D_MODEL, D_MODEL);
    cudaStreamWaitEvent(0, evK2, 0);
    flash_mma<true><<<gAttnH, 256, FLASH_SMEM>>>(qh, kh2, mask, actH);
    cudaStreamWaitEvent(0, evO2, 0);
    mma_gemm<0><<<gPh, 256, GEMM_SMEM>>>(actH, wO2, nullptr, pt1, nullptr, D_MODEL, D_MODEL);
    add_ln_kernel<true><<<SEQ, 256>>>(px1, pt1, g2, b2, px2, actH);
    cudaStreamWaitEvent(0, evF1, 0);
    mma_gemm<3><<<gF1h, 256, GEMM_SMEM>>>(actH, wF1, ffb1, nullptr, hid, MLP, D_MODEL);
    cudaStreamWaitEvent(0, evF2, 0);
    mma_gemm<2><<<gPh, 256, GEMM_SMEM>>>(hid, wF2, ffb2, pt1, nullptr, D_MODEL, MLP);
    add_ln_kernel<false><<<SEQ, 256>>>(px2, pt1, g3, b3, (float*)d_out, nullptr);
    cudaStreamWaitEvent(0, evTailB, 0);
}